// round 12
// baseline (speedup 1.0000x reference)
#include <cuda_runtime.h>
#include <cstdint>

// Problem constants: B=2, T=2048, C=1024, H=16, D=64
__device__ float g_qkv[4096 * 3072];
__device__ float g_attn[4096 * 1024];
__device__ float g_wt[3072 * 1024 + 1024 * 1024];   // W_qkv^T then W_out^T (tf32)
__device__ float g_xr[4096 * 1024];                 // x rounded to tf32

// ---------------------------------------------------------------------------
// helpers
// ---------------------------------------------------------------------------
static __device__ __forceinline__ uint32_t f2tf32(float f) {
    uint32_t u;
    asm("cvt.rna.tf32.f32 %0, %1;" : "=r"(u) : "f"(f));
    return u;
}
static __device__ __forceinline__ float tf32r(float f) {
    return __uint_as_float(f2tf32(f));
}
static __device__ __forceinline__ void mma_tf32(
    float c[4], uint32_t a0, uint32_t a1, uint32_t a2, uint32_t a3,
    uint32_t b0, uint32_t b1)
{
    asm volatile(
        "mma.sync.aligned.m16n8k8.row.col.f32.tf32.tf32.f32 "
        "{%0,%1,%2,%3}, {%4,%5,%6,%7}, {%8,%9}, {%0,%1,%2,%3};"
        : "+f"(c[0]), "+f"(c[1]), "+f"(c[2]), "+f"(c[3])
        : "r"(a0), "r"(a1), "r"(a2), "r"(a3), "r"(b0), "r"(b1));
}
static __device__ __forceinline__ uint32_t smem_u32(const void* p) {
    uint32_t a;
    asm("{ .reg .u64 t; cvta.to.shared.u64 t, %1; cvt.u32.u64 %0, t; }"
        : "=r"(a) : "l"(p));
    return a;
}
static __device__ __forceinline__ void cp16(uint32_t dst, const void* src) {
    asm volatile("cp.async.cg.shared.global [%0], [%1], 16;" :: "r"(dst), "l"(src));
}
#define CP_COMMIT() asm volatile("cp.async.commit_group;" ::: "memory")
#define CP_WAIT0()  asm volatile("cp.async.wait_group 0;" ::: "memory")

// ---------------------------------------------------------------------------
// Elementwise tf32 rounding: out[i] = tf32(in[i])
// ---------------------------------------------------------------------------
__global__ void round_tf32_kernel(const float* __restrict__ in, float* __restrict__ out, int n)
{
    int i = (blockIdx.x * blockDim.x + threadIdx.x) * 4;
    if (i < n) {
        float4 v = *(const float4*)(in + i);
        float4 r = { tf32r(v.x), tf32r(v.y), tf32r(v.z), tf32r(v.w) };
        *(float4*)(out + i) = r;
    }
}

// ---------------------------------------------------------------------------
// Transpose + tf32 round: out[N,K] = tf32(in[K,N]).
// ---------------------------------------------------------------------------
__global__ void transpose_kernel(const float* __restrict__ in, float* __restrict__ out,
                                 int R, int Ccols)
{
    __shared__ float tile[32][33];
    int c = blockIdx.x * 32 + threadIdx.x;
    int r0 = blockIdx.y * 32;
#pragma unroll
    for (int i = 0; i < 32; i += 8)
        tile[threadIdx.y + i][threadIdx.x] =
            tf32r(in[(size_t)(r0 + threadIdx.y + i) * Ccols + c]);
    __syncthreads();
    int oc = blockIdx.y * 32 + threadIdx.x;
    int or0 = blockIdx.x * 32;
#pragma unroll
    for (int i = 0; i < 32; i += 8)
        out[(size_t)(or0 + threadIdx.y + i) * R + oc] = tile[threadIdx.x][threadIdx.y + i];
}

// ---------------------------------------------------------------------------
// mma.sync tf32 GEMM, cp.async double-buffered: C = A * BT^T + bias
// A, BT must be PRE-ROUNDED to tf32. round_out=1 -> tf32-rounded output.
// ---------------------------------------------------------------------------
constexpr int ASTR = 36;
constexpr int GEMM_SMEM = 2 * 2 * 128 * ASTR * (int)sizeof(float);   // 73728

__global__ __launch_bounds__(256)
void gemm_mma_kernel(const float* __restrict__ A, const float* __restrict__ BT,
                     const float* __restrict__ bias, float* __restrict__ C,
                     int M, int N, int K, int round_out)
{
    extern __shared__ float sm[];
    float* AsBase = sm;                      // [2][128][ASTR]
    float* BsBase = sm + 2 * 128 * ASTR;     // [2][128][ASTR]
    const uint32_t smem0 = smem_u32(sm);

    const int tid  = threadIdx.x;
    const int wid  = tid >> 5;
    const int lane = tid & 31;
    const int gid  = lane >> 2;
    const int tig  = lane & 3;
    const int warp_m = wid & 1;
    const int warp_n = wid >> 1;

    const int row0 = blockIdx.y * 128;
    const int n0   = blockIdx.x * 128;

    // cp.async mapping: 2 threads per row, 4x16B chunks each (32 floats/row)
    const int arow = tid >> 1;               // 0..127
    const int ahalf = (tid & 1) * 16;        // float offset 0 or 16
    const float* Ab = A  + (size_t)(row0 + arow) * K + ahalf;
    const float* Bb = BT + (size_t)(n0  + arow) * K + ahalf;
    const uint32_t adst0 = smem0 + (uint32_t)(arow * ASTR + ahalf) * 4;
    const uint32_t bdst0 = adst0 + (uint32_t)(2 * 128 * ASTR) * 4;
    const uint32_t bufstep = (uint32_t)(128 * ASTR) * 4;

    float acc[4][4][4];
#pragma unroll
    for (int mi = 0; mi < 4; mi++)
#pragma unroll
        for (int ni = 0; ni < 4; ni++)
#pragma unroll
            for (int r = 0; r < 4; r++) acc[mi][ni][r] = 0.0f;

    const int nchunk = K / 32;

    // prologue: issue chunk 0 into buffer 0
#pragma unroll
    for (int i = 0; i < 4; i++) {
        cp16(adst0 + i * 16, (const char*)Ab + i * 16);
        cp16(bdst0 + i * 16, (const char*)Bb + i * 16);
    }
    CP_COMMIT();

    for (int c = 0; c < nchunk; c++) {
        const int buf = c & 1;
        const float* As = AsBase + buf * 128 * ASTR;
        const float* Bs = BsBase + buf * 128 * ASTR;

        CP_WAIT0();
        __syncthreads();   // chunk c visible; compute on other buf finished

        if (c + 1 < nchunk) {
            const char* as = (const char*)(Ab + (size_t)(c + 1) * 32);
            const char* bs = (const char*)(Bb + (size_t)(c + 1) * 32);
            const uint32_t ad = adst0 + (buf ^ 1) * bufstep;
            const uint32_t bd = bdst0 + (buf ^ 1) * bufstep;
#pragma unroll
            for (int i = 0; i < 4; i++) {
                cp16(ad + i * 16, as + i * 16);
                cp16(bd + i * 16, bs + i * 16);
            }
            CP_COMMIT();
        }

        const int mbase = warp_m * 64;
        const int nbase = warp_n * 32;
#pragma unroll
        for (int kk = 0; kk < 32; kk += 8) {
            uint32_t afr[4][4];
#pragma unroll
            for (int mi = 0; mi < 4; mi++) {
                const int r = mbase + mi * 16;
                afr[mi][0] = __float_as_uint(As[(r + gid)     * ASTR + kk + tig]);
                afr[mi][1] = __float_as_uint(As[(r + gid + 8) * ASTR + kk + tig]);
                afr[mi][2] = __float_as_uint(As[(r + gid)     * ASTR + kk + tig + 4]);
                afr[mi][3] = __float_as_uint(As[(r + gid + 8) * ASTR + kk + tig + 4]);
            }
            uint32_t bfr[4][2];
#pragma unroll
            for (int ni = 0; ni < 4; ni++) {
                const int n = nbase + ni * 8 + gid;
                bfr[ni][0] = __float_as_uint(Bs[n * ASTR + kk + tig]);
                bfr[ni][1] = __float_as_uint(Bs[n * ASTR + kk + tig + 4]);
            }
#pragma unroll
            for (int mi = 0; mi < 4; mi++)
#pragma unroll
                for (int ni = 0; ni < 4; ni++)
                    mma_tf32(acc[mi][ni], afr[mi][0], afr[mi][1], afr[mi][2], afr[mi][3],
                             bfr[ni][0], bfr[ni][1]);
        }
    }

#pragma unroll
    for (int mi = 0; mi < 4; mi++) {
        const int r = row0 + warp_m * 64 + mi * 16 + gid;
#pragma unroll
        for (int ni = 0; ni < 4; ni++) {
            const int cc = n0 + warp_n * 32 + ni * 8 + tig * 2;
            const float b0 = bias[cc], b1 = bias[cc + 1];
            float2 v0, v1;
            if (round_out) {
                v0 = make_float2(tf32r(acc[mi][ni][0] + b0), tf32r(acc[mi][ni][1] + b1));
                v1 = make_float2(tf32r(acc[mi][ni][2] + b0), tf32r(acc[mi][ni][3] + b1));
            } else {
                v0 = make_float2(acc[mi][ni][0] + b0, acc[mi][ni][1] + b1);
                v1 = make_float2(acc[mi][ni][2] + b0, acc[mi][ni][3] + b1);
            }
            *(float2*)(C + (size_t)r * N + cc)       = v0;
            *(float2*)(C + (size_t)(r + 8) * N + cc) = v1;
        }
    }
}

// ---------------------------------------------------------------------------
// Flash attention (causal), mma.sync tf32. 128-row Q tiles, 8 warps.
// cp.async double-buffered K/V (qkv pre-rounded tf32). K stride 68
// (pattern 4*gid+tig conflict-free), V kept [key][d] with stride 72
// (pattern 8*tig+gid conflict-free for PV B-fragments).
// ---------------------------------------------------------------------------
constexpr int KSTR = 68;
constexpr int VSTR = 72;
constexpr int FL5_SMEM = (2 * 64 * KSTR + 2 * 64 * VSTR + 128 * KSTR) * (int)sizeof(float); // 106496

__global__ __launch_bounds__(256, 2)
void flash_mma_kernel(const float* __restrict__ qkv, float* __restrict__ out)
{
    extern __shared__ float sm[];
    float* KBuf = sm;                        // [2][64][KSTR]
    float* VBuf = sm + 2 * 64 * KSTR;        // [2][64][VSTR]
    float* Ps   = VBuf + 2 * 64 * VSTR;      // [128][KSTR]
    const uint32_t smem0 = smem_u32(sm);
    const uint32_t voff  = (uint32_t)(2 * 64 * KSTR) * 4;

    const int tid  = threadIdx.x;
    const int wid  = tid >> 5;
    const int lane = tid & 31;
    const int gid  = lane >> 2;
    const int tig  = lane & 3;

    const int qx = 15 - blockIdx.x;          // heavy tiles first
    const int bh = blockIdx.y;
    const int b  = bh >> 4;
    const int h  = bh & 15;
    const int q0 = qx * 128;
    const int rs = 3072;
    const float* base = qkv + (size_t)(b * 2048) * rs + h * 64;

    const int ckey = tid >> 2;               // 64 keys, 4 threads/key
    const int c4   = tid & 3;
    const int nkt  = 2 * qx + 2;

    // issue K/V tile 0 into buffer 0
    {
        const char* ksrc = (const char*)(base + (size_t)ckey * rs + 1024);
        const char* vsrc = (const char*)(base + (size_t)ckey * rs + 2048);
        const uint32_t kdst = smem0 + (uint32_t)(ckey * KSTR) * 4;
        const uint32_t vdst = smem0 + voff + (uint32_t)(ckey * VSTR) * 4;
#pragma unroll
        for (int i = 0; i < 4; i++) {
            const int chunk = c4 * 4 + i;
            cp16(kdst + chunk * 16, ksrc + chunk * 16);
            cp16(vdst + chunk * 16, vsrc + chunk * 16);
        }
        CP_COMMIT();
    }

    // ---- stage Q tile (exact x0.125; qkv already tf32) ----
#pragma unroll
    for (int i = 0; i < 8; i++) {
        int idx = tid + i * 256;
        int row = idx >> 4;
        int dg  = (idx & 15) * 4;
        float4 v = *(const float4*)(base + (size_t)(q0 + row) * rs + dg);
        float* d = &Ps[row * KSTR + dg];
        d[0] = v.x * 0.125f; d[1] = v.y * 0.125f;
        d[2] = v.z * 0.125f; d[3] = v.w * 0.125f;
    }
    __syncthreads();

    const int lr0 = wid * 16 + gid;
    const int lr1 = lr0 + 8;
    uint32_t qf[8][4];
#pragma unroll
    for (int kk = 0; kk < 8; kk++) {
        qf[kk][0] = __float_as_uint(Ps[lr0 * KSTR + kk * 8 + tig]);
        qf[kk][1] = __float_as_uint(Ps[lr1 * KSTR + kk * 8 + tig]);
        qf[kk][2] = __float_as_uint(Ps[lr0 * KSTR + kk * 8 + tig + 4]);
        qf[kk][3] = __float_as_uint(Ps[lr1 * KSTR + kk * 8 + tig + 4]);
    }

    float of[8][4];
#pragma unroll
    for (int ni = 0; ni < 8; ni++)
#pragma unroll
        for (int r = 0; r < 4; r++) of[ni][r] = 0.0f;
    float m0 = -1e30f, m1 = -1e30f, l0 = 0.0f, l1 = 0.0f;

    const int row0g = q0 + lr0;
    const int row1g = row0g + 8;

    for (int kt = 0; kt < nkt; kt++) {
        const int buf = kt & 1;
        const float* Ks = KBuf + buf * 64 * KSTR;
        const float* Vs = VBuf + buf * 64 * VSTR;

        CP_WAIT0();
        __syncthreads();

        if (kt + 1 < nkt) {
            const char* ksrc = (const char*)(base + (size_t)((kt + 1) * 64 + ckey) * rs + 1024);
            const char* vsrc = (const char*)(base + (size_t)((kt + 1) * 64 + ckey) * rs + 2048);
            const uint32_t kdst = smem0 + (uint32_t)(((buf ^ 1) * 64 + ckey) * KSTR) * 4;
            const uint32_t vdst = smem0 + voff + (uint32_t)(((buf ^ 1) * 64 + ckey) * VSTR) * 4;
#pragma unroll
            for (int i = 0; i < 4; i++) {
                const int chunk = c4 * 4 + i;
                cp16(kdst + chunk * 16, ksrc + chunk * 16);
                cp16(vdst + chunk * 16, vsrc + chunk * 16);
            }
            CP_COMMIT();
        }

        // ---- S = Q K^T ----
        float sf[8][4];
#pragma unroll
        for (int ni = 0; ni < 8; ni++)
#pragma unroll
            for (int r = 0; r < 4; r++) sf[ni][r] = 0.0f;

#pragma unroll
        for (int kk = 0; kk < 8; kk++) {
            uint32_t bfr[8][2];
#pragma unroll
            for (int ni = 0; ni < 8; ni++) {
                bfr[ni][0] = __float_as_uint(Ks[(ni * 8 + gid) * KSTR + kk * 8 + tig]);
                bfr[ni][1] = __float_as_uint(Ks[(ni * 8 + gid) * KSTR + kk * 8 + tig + 4]);
            }
#pragma unroll
            for (int ni = 0; ni < 8; ni++)
                mma_tf32(sf[ni], qf[kk][0], qf[kk][1], qf[kk][2], qf[kk][3],
                         bfr[ni][0], bfr[ni][1]);
        }

        // ---- causal mask (diagonal tiles only) ----
        if (kt >= 2 * qx) {
            const int cb = kt * 64 + tig * 2;
#pragma unroll
            for (int ni = 0; ni < 8; ni++) {
                const int c0 = cb + ni * 8, c1 = c0 + 1;
                if (c0 > row0g) sf[ni][0] = -1e30f;
                if (c1 > row0g) sf[ni][1] = -1e30f;
                if (c0 > row1g) sf[ni][2] = -1e30f;
                if (c1 > row1g) sf[ni][3] = -1e30f;
            }
        }

        // ---- online softmax ----
        float mx0 = -1e30f, mx1 = -1e30f;
#pragma unroll
        for (int ni = 0; ni < 8; ni++) {
            mx0 = fmaxf(mx0, fmaxf(sf[ni][0], sf[ni][1]));
            mx1 = fmaxf(mx1, fmaxf(sf[ni][2], sf[ni][3]));
        }
        mx0 = fmaxf(mx0, __shfl_xor_sync(0xffffffffu, mx0, 1));
        mx0 = fmaxf(mx0, __shfl_xor_sync(0xffffffffu, mx0, 2));
        mx1 = fmaxf(mx1, __shfl_xor_sync(0xffffffffu, mx1, 1));
        mx1 = fmaxf(mx1, __shfl_xor_sync(0xffffffffu, mx1, 2));

        const float mn0 = fmaxf(m0, mx0);
        const float mn1 = fmaxf(m1, mx1);
        const float corr0 = __expf(m0 - mn0);
        const float corr1 = __expf(m1 - mn1);
        m0 = mn0; m1 = mn1;

        float ls0 = 0.0f, ls1 = 0.0f;
#pragma unroll
        for (int ni = 0; ni < 8; ni++) {
            sf[ni][0] = __expf(sf[ni][0] - mn0); ls0 += sf[ni][0];
            sf[ni][1] = __expf(sf[ni][1] - mn0); ls0 += sf[ni][1];
            sf[ni][2] = __expf(sf[ni][2] - mn1); ls1 += sf[ni][2];
            sf[ni][3] = __expf(sf[ni][3] - mn1); ls1 += sf[ni][3];
        }
        ls0 += __shfl_xor_sync(0xffffffffu, ls0, 1);
        ls0 += __shfl_xor_sync(0xffffffffu, ls0, 2);
        ls1 += __shfl_xor_sync(0xffffffffu, ls1, 1);
        ls1 += __shfl_xor_sync(0xffffffffu, ls1, 2);
        l0 = l0 * corr0 + ls0;
        l1 = l1 * corr1 + ls1;

#pragma unroll
        for (int ni = 0; ni < 8; ni++) {
            of[ni][0] *= corr0; of[ni][1] *= corr0;
            of[ni][2] *= corr1; of[ni][3] *= corr1;
        }

        // ---- stage P (tf32) for A-operand re-fragmentation ----
#pragma unroll
        for (int ni = 0; ni < 8; ni++) {
            float2 p0 = { tf32r(sf[ni][0]), tf32r(sf[ni][1]) };
            float2 p1 = { tf32r(sf[ni][2]), tf32r(sf[ni][3]) };
            *(float2*)&Ps[lr0 * KSTR + ni * 8 + tig * 2] = p0;
            *(float2*)&Ps[lr1 * KSTR + ni * 8 + tig * 2] = p1;
        }
        __syncthreads();

        // ---- O += P V  (V[key][d], VSTR=72 -> conflict-free B-frags) ----
#pragma unroll
        for (int kk = 0; kk < 8; kk++) {
            uint32_t pa0 = __float_as_uint(Ps[lr0 * KSTR + kk * 8 + tig]);
            uint32_t pa1 = __float_as_uint(Ps[lr1 * KSTR + kk * 8 + tig]);
            uint32_t pa2 = __float_as_uint(Ps[lr0 * KSTR + kk * 8 + tig + 4]);
            uint32_t pa3 = __float_as_uint(Ps[lr1 * KSTR + kk * 8 + tig + 4]);
#pragma unroll
            for (int ni = 0; ni < 8; ni++) {
                uint32_t b0 = __float_as_uint(Vs[(kk * 8 + tig)     * VSTR + ni * 8 + gid]);
                uint32_t b1 = __float_as_uint(Vs[(kk * 8 + tig + 4) * VSTR + ni * 8 + gid]);
                mma_tf32(of[ni], pa0, pa1, pa2, pa3, b0, b1);
            }
        }
    }

    // ---- epilogue (tf32-rounded: consumed by cp.async GEMM) ----
    const float inv0 = 1.0f / l0;
    const float inv1 = 1.0f / l1;
    float* o0 = out + (size_t)(b * 2048 + row0g) * 1024 + h * 64;
    float* o1 = o0 + (size_t)8 * 1024;
#pragma unroll
    for (int ni = 0; ni < 8; ni++) {
        float2 v0 = { tf32r(of[ni][0] * inv0), tf32r(of[ni][1] * inv0) };
        float2 v1 = { tf32r(of[ni][2] * inv1), tf32r(of[ni][3] * inv1) };
        *(float2*)(o0 + ni * 8 + tig * 2) = v0;
        *(float2*)(o1 + ni * 8 + tig * 2) = v1;
    }
}

// ---------------------------------------------------------------------------
// kernel_launch
// ---------------------------------------------------------------------------
extern "C" void kernel_launch(void* const* d_in, const int* in_sizes, int n_in,
                              void* d_out, int out_size)
{
    const float* x     = (const float*)d_in[0];   // [4096, 1024]
    const float* w_qkv = (const float*)d_in[1];   // [1024, 3072]
    const float* b_qkv = (const float*)d_in[2];   // [3072]
    const float* w_out = (const float*)d_in[3];   // [1024, 1024]
    const float* b_out = (const float*)d_in[4];   // [1024]
    float* out = (float*)d_out;                   // [4096, 1024]

    float *qkv = nullptr, *attn = nullptr, *wt = nullptr, *xr = nullptr;
    cudaGetSymbolAddress((void**)&qkv,  g_qkv);
    cudaGetSymbolAddress((void**)&attn, g_attn);
    cudaGetSymbolAddress((void**)&wt,   g_wt);
    cudaGetSymbolAddress((void**)&xr,   g_xr);
    float* wt_qkv = wt;                      // [3072, 1024]
    float* wt_out = wt + 3072 * 1024;        // [1024, 1024]

    cudaFuncSetAttribute(gemm_mma_kernel,
                         cudaFuncAttributeMaxDynamicSharedMemorySize, GEMM_SMEM);
    cudaFuncSetAttribute(flash_mma_kernel,
                         cudaFuncAttributeMaxDynamicSharedMemorySize, FL5_SMEM);

    // 0) pre-round x; transpose+round weights
    round_tf32_kernel<<<4096, 256>>>(x, xr, 4096 * 1024);
    {
        dim3 blk(32, 8);
        transpose_kernel<<<dim3(3072 / 32, 1024 / 32), blk>>>(w_qkv, wt_qkv, 1024, 3072);
        transpose_kernel<<<dim3(1024 / 32, 1024 / 32), blk>>>(w_out, wt_out, 1024, 1024);
    }

    // 1) QKV projection (tf32-rounded output for flash)
    {
        dim3 grid(3072 / 128, 4096 / 128);
        gemm_mma_kernel<<<grid, 256, GEMM_SMEM>>>(xr, wt_qkv, b_qkv, qkv, 4096, 3072, 1024, 1);
    }

    // 2) Causal flash attention -> g_attn (tf32-rounded)
    {
        dim3 grid(16, 2 * 16);
        flash_mma_kernel<<<grid, 256, FL5_SMEM>>>(qkv, attn);
    }

    // 3) Output projection (full-precision output)
    {
        dim3 grid(1024 / 128, 4096 / 128);
        gemm_mma_kernel<<<grid, 256, GEMM_SMEM>>>(attn, wt_out, b_out, out, 4096, 1024, 1024, 0);
    }
}

// round 13
// speedup vs baseline: 1.2983x; 1.2983x over previous
#include <cuda_runtime.h>
#include <cstdint>

// Problem constants: B=2, T=2048, C=1024, H=16, D=64
__device__ float g_qkv[4096 * 3072];
__device__ float g_attn[4096 * 1024];
__device__ float g_wt[3072 * 1024 + 1024 * 1024];   // W_qkv^T then W_out^T (tf32)
__device__ float g_xr[4096 * 1024];                 // x rounded to tf32

// ---------------------------------------------------------------------------
// helpers
// ---------------------------------------------------------------------------
static __device__ __forceinline__ uint32_t f2tf32(float f) {
    uint32_t u;
    asm("cvt.rna.tf32.f32 %0, %1;" : "=r"(u) : "f"(f));
    return u;
}
static __device__ __forceinline__ float tf32r(float f) {
    return __uint_as_float(f2tf32(f));
}
static __device__ __forceinline__ void mma_tf32(
    float c[4], uint32_t a0, uint32_t a1, uint32_t a2, uint32_t a3,
    uint32_t b0, uint32_t b1)
{
    asm volatile(
        "mma.sync.aligned.m16n8k8.row.col.f32.tf32.tf32.f32 "
        "{%0,%1,%2,%3}, {%4,%5,%6,%7}, {%8,%9}, {%0,%1,%2,%3};"
        : "+f"(c[0]), "+f"(c[1]), "+f"(c[2]), "+f"(c[3])
        : "r"(a0), "r"(a1), "r"(a2), "r"(a3), "r"(b0), "r"(b1));
}
static __device__ __forceinline__ uint32_t smem_u32(const void* p) {
    uint32_t a;
    asm("{ .reg .u64 t; cvta.to.shared.u64 t, %1; cvt.u32.u64 %0, t; }"
        : "=r"(a) : "l"(p));
    return a;
}
static __device__ __forceinline__ void cp16(uint32_t dst, const void* src) {
    asm volatile("cp.async.cg.shared.global [%0], [%1], 16;" :: "r"(dst), "l"(src));
}
#define CP_COMMIT() asm volatile("cp.async.commit_group;" ::: "memory")
#define CP_WAIT0()  asm volatile("cp.async.wait_group 0;" ::: "memory")

// ---------------------------------------------------------------------------
// Elementwise tf32 rounding: out[i] = tf32(in[i])
// ---------------------------------------------------------------------------
__global__ void round_tf32_kernel(const float* __restrict__ in, float* __restrict__ out, int n)
{
    int i = (blockIdx.x * blockDim.x + threadIdx.x) * 4;
    if (i < n) {
        float4 v = *(const float4*)(in + i);
        float4 r = { tf32r(v.x), tf32r(v.y), tf32r(v.z), tf32r(v.w) };
        *(float4*)(out + i) = r;
    }
}

// ---------------------------------------------------------------------------
// Transpose + tf32 round: out[N,K] = tf32(in[K,N]).
// ---------------------------------------------------------------------------
__global__ void transpose_kernel(const float* __restrict__ in, float* __restrict__ out,
                                 int R, int Ccols)
{
    __shared__ float tile[32][33];
    int c = blockIdx.x * 32 + threadIdx.x;
    int r0 = blockIdx.y * 32;
#pragma unroll
    for (int i = 0; i < 32; i += 8)
        tile[threadIdx.y + i][threadIdx.x] =
            tf32r(in[(size_t)(r0 + threadIdx.y + i) * Ccols + c]);
    __syncthreads();
    int oc = blockIdx.y * 32 + threadIdx.x;
    int or0 = blockIdx.x * 32;
#pragma unroll
    for (int i = 0; i < 32; i += 8)
        out[(size_t)(or0 + threadIdx.y + i) * R + oc] = tile[threadIdx.x][threadIdx.y + i];
}

// ---------------------------------------------------------------------------
// mma.sync tf32 GEMM, cp.async double-buffered, COALESCED loader:
// per cp.async instruction a warp covers 4 rows x 128B contiguous.
// A, BT must be PRE-ROUNDED to tf32. round_out=1 -> tf32-rounded output.
// ---------------------------------------------------------------------------
constexpr int ASTR = 36;
constexpr int GEMM_SMEM = 2 * 2 * 128 * ASTR * (int)sizeof(float);   // 73728

__global__ __launch_bounds__(256)
void gemm_mma_kernel(const float* __restrict__ A, const float* __restrict__ BT,
                     const float* __restrict__ bias, float* __restrict__ C,
                     int M, int N, int K, int round_out)
{
    extern __shared__ float sm[];
    float* AsBase = sm;                      // [2][128][ASTR]
    float* BsBase = sm + 2 * 128 * ASTR;     // [2][128][ASTR]
    const uint32_t smem0 = smem_u32(sm);

    const int tid  = threadIdx.x;
    const int wid  = tid >> 5;
    const int lane = tid & 31;
    const int gid  = lane >> 2;
    const int tig  = lane & 3;
    const int warp_m = wid & 1;
    const int warp_n = wid >> 1;

    const int row0 = blockIdx.y * 128;
    const int n0   = blockIdx.x * 128;

    // coalesced cp.async mapping: 8 threads/row, 16B each; 4 row-groups of 32
    const int arow = tid >> 3;               // 0..31
    const int acol = (tid & 7) * 4;          // float offset 0..28
    const float* Ab = A  + (size_t)(row0 + arow) * K + acol;
    const float* Bb = BT + (size_t)(n0  + arow) * K + acol;
    const uint32_t adst0 = smem0 + (uint32_t)(arow * ASTR + acol) * 4;
    const uint32_t bdst0 = adst0 + (uint32_t)(2 * 128 * ASTR) * 4;
    const uint32_t rstep = (uint32_t)(32 * ASTR) * 4;    // 32 rows of smem
    const uint32_t bufstep = (uint32_t)(128 * ASTR) * 4;

    float acc[4][4][4];
#pragma unroll
    for (int mi = 0; mi < 4; mi++)
#pragma unroll
        for (int ni = 0; ni < 4; ni++)
#pragma unroll
            for (int r = 0; r < 4; r++) acc[mi][ni][r] = 0.0f;

    const int nchunk = K / 32;

    // prologue: issue chunk 0 into buffer 0
#pragma unroll
    for (int it = 0; it < 4; it++) {
        cp16(adst0 + it * rstep, Ab + (size_t)(it * 32) * K);
        cp16(bdst0 + it * rstep, Bb + (size_t)(it * 32) * K);
    }
    CP_COMMIT();

    for (int c = 0; c < nchunk; c++) {
        const int buf = c & 1;
        const float* As = AsBase + buf * 128 * ASTR;
        const float* Bs = BsBase + buf * 128 * ASTR;

        CP_WAIT0();
        __syncthreads();   // chunk c visible; compute on other buf finished

        if (c + 1 < nchunk) {
            const float* as = Ab + (size_t)(c + 1) * 32;
            const float* bs = Bb + (size_t)(c + 1) * 32;
            const uint32_t ad = adst0 + (buf ^ 1) * bufstep;
            const uint32_t bd = bdst0 + (buf ^ 1) * bufstep;
#pragma unroll
            for (int it = 0; it < 4; it++) {
                cp16(ad + it * rstep, as + (size_t)(it * 32) * K);
                cp16(bd + it * rstep, bs + (size_t)(it * 32) * K);
            }
            CP_COMMIT();
        }

        const int mbase = warp_m * 64;
        const int nbase = warp_n * 32;
#pragma unroll
        for (int kk = 0; kk < 32; kk += 8) {
            uint32_t afr[4][4];
#pragma unroll
            for (int mi = 0; mi < 4; mi++) {
                const int r = mbase + mi * 16;
                afr[mi][0] = __float_as_uint(As[(r + gid)     * ASTR + kk + tig]);
                afr[mi][1] = __float_as_uint(As[(r + gid + 8) * ASTR + kk + tig]);
                afr[mi][2] = __float_as_uint(As[(r + gid)     * ASTR + kk + tig + 4]);
                afr[mi][3] = __float_as_uint(As[(r + gid + 8) * ASTR + kk + tig + 4]);
            }
            uint32_t bfr[4][2];
#pragma unroll
            for (int ni = 0; ni < 4; ni++) {
                const int n = nbase + ni * 8 + gid;
                bfr[ni][0] = __float_as_uint(Bs[n * ASTR + kk + tig]);
                bfr[ni][1] = __float_as_uint(Bs[n * ASTR + kk + tig + 4]);
            }
#pragma unroll
            for (int mi = 0; mi < 4; mi++)
#pragma unroll
                for (int ni = 0; ni < 4; ni++)
                    mma_tf32(acc[mi][ni], afr[mi][0], afr[mi][1], afr[mi][2], afr[mi][3],
                             bfr[ni][0], bfr[ni][1]);
        }
    }

#pragma unroll
    for (int mi = 0; mi < 4; mi++) {
        const int r = row0 + warp_m * 64 + mi * 16 + gid;
#pragma unroll
        for (int ni = 0; ni < 4; ni++) {
            const int cc = n0 + warp_n * 32 + ni * 8 + tig * 2;
            const float b0 = bias[cc], b1 = bias[cc + 1];
            float2 v0, v1;
            if (round_out) {
                v0 = make_float2(tf32r(acc[mi][ni][0] + b0), tf32r(acc[mi][ni][1] + b1));
                v1 = make_float2(tf32r(acc[mi][ni][2] + b0), tf32r(acc[mi][ni][3] + b1));
            } else {
                v0 = make_float2(acc[mi][ni][0] + b0, acc[mi][ni][1] + b1);
                v1 = make_float2(acc[mi][ni][2] + b0, acc[mi][ni][3] + b1);
            }
            *(float2*)(C + (size_t)r * N + cc)       = v0;
            *(float2*)(C + (size_t)(r + 8) * N + cc) = v1;
        }
    }
}

// ---------------------------------------------------------------------------
// Flash attention (causal), mma.sync tf32. 128-row Q tiles, 8 warps.
// cp.async double-buffered K/V with COALESCED loader (16 threads/row, 16B
// each -> warp covers 2 full 256B rows). K stride 68 (QK^T B-frags
// conflict-free), V [key][d] stride 72 (PV B-frags conflict-free).
// ---------------------------------------------------------------------------
constexpr int KSTR = 68;
constexpr int VSTR = 72;
constexpr int FL5_SMEM = (2 * 64 * KSTR + 2 * 64 * VSTR + 128 * KSTR) * (int)sizeof(float); // 106496

__global__ __launch_bounds__(256, 2)
void flash_mma_kernel(const float* __restrict__ qkv, float* __restrict__ out)
{
    extern __shared__ float sm[];
    float* KBuf = sm;                        // [2][64][KSTR]
    float* VBuf = sm + 2 * 64 * KSTR;        // [2][64][VSTR]
    float* Ps   = VBuf + 2 * 64 * VSTR;      // [128][KSTR]
    const uint32_t smem0 = smem_u32(sm);
    const uint32_t voff  = (uint32_t)(2 * 64 * KSTR) * 4;

    const int tid  = threadIdx.x;
    const int wid  = tid >> 5;
    const int lane = tid & 31;
    const int gid  = lane >> 2;
    const int tig  = lane & 3;

    const int qx = 15 - blockIdx.x;          // heavy tiles first
    const int bh = blockIdx.y;
    const int b  = bh >> 4;
    const int h  = bh & 15;
    const int q0 = qx * 128;
    const int rs = 3072;
    const float* base = qkv + (size_t)(b * 2048) * rs + h * 64;

    // coalesced cp.async mapping: 16 threads/row (16B each), 4 row-groups of 16
    const int ckey = tid >> 4;               // 0..15
    const int c16f = (tid & 15) * 4;         // float offset 0..60
    const int nkt  = 2 * qx + 2;

    // issue K/V tile 0 into buffer 0
#pragma unroll
    for (int it = 0; it < 4; it++) {
        const int key = ckey + it * 16;
        const float* ksrc = base + (size_t)key * rs + 1024 + c16f;
        cp16(smem0 + (uint32_t)(key * KSTR + c16f) * 4, ksrc);
        cp16(smem0 + voff + (uint32_t)(key * VSTR + c16f) * 4, ksrc + 1024);
    }
    CP_COMMIT();

    // ---- stage Q tile (exact x0.125; qkv already tf32) ----
#pragma unroll
    for (int i = 0; i < 8; i++) {
        int idx = tid + i * 256;
        int row = idx >> 4;
        int dg  = (idx & 15) * 4;
        float4 v = *(const float4*)(base + (size_t)(q0 + row) * rs + dg);
        float* d = &Ps[row * KSTR + dg];
        d[0] = v.x * 0.125f; d[1] = v.y * 0.125f;
        d[2] = v.z * 0.125f; d[3] = v.w * 0.125f;
    }
    __syncthreads();

    const int lr0 = wid * 16 + gid;
    const int lr1 = lr0 + 8;
    uint32_t qf[8][4];
#pragma unroll
    for (int kk = 0; kk < 8; kk++) {
        qf[kk][0] = __float_as_uint(Ps[lr0 * KSTR + kk * 8 + tig]);
        qf[kk][1] = __float_as_uint(Ps[lr1 * KSTR + kk * 8 + tig]);
        qf[kk][2] = __float_as_uint(Ps[lr0 * KSTR + kk * 8 + tig + 4]);
        qf[kk][3] = __float_as_uint(Ps[lr1 * KSTR + kk * 8 + tig + 4]);
    }

    float of[8][4];
#pragma unroll
    for (int ni = 0; ni < 8; ni++)
#pragma unroll
        for (int r = 0; r < 4; r++) of[ni][r] = 0.0f;
    float m0 = -1e30f, m1 = -1e30f, l0 = 0.0f, l1 = 0.0f;

    const int row0g = q0 + lr0;
    const int row1g = row0g + 8;

    for (int kt = 0; kt < nkt; kt++) {
        const int buf = kt & 1;
        const float* Ks = KBuf + buf * 64 * KSTR;
        const float* Vs = VBuf + buf * 64 * VSTR;

        CP_WAIT0();
        __syncthreads();

        if (kt + 1 < nkt) {
            const int kb = (buf ^ 1) * 64;
#pragma unroll
            for (int it = 0; it < 4; it++) {
                const int key = ckey + it * 16;
                const float* ksrc = base + (size_t)((kt + 1) * 64 + key) * rs + 1024 + c16f;
                cp16(smem0 + (uint32_t)((kb + key) * KSTR + c16f) * 4, ksrc);
                cp16(smem0 + voff + (uint32_t)((kb + key) * VSTR + c16f) * 4, ksrc + 1024);
            }
            CP_COMMIT();
        }

        // ---- S = Q K^T ----
        float sf[8][4];
#pragma unroll
        for (int ni = 0; ni < 8; ni++)
#pragma unroll
            for (int r = 0; r < 4; r++) sf[ni][r] = 0.0f;

#pragma unroll
        for (int kk = 0; kk < 8; kk++) {
            uint32_t bfr[8][2];
#pragma unroll
            for (int ni = 0; ni < 8; ni++) {
                bfr[ni][0] = __float_as_uint(Ks[(ni * 8 + gid) * KSTR + kk * 8 + tig]);
                bfr[ni][1] = __float_as_uint(Ks[(ni * 8 + gid) * KSTR + kk * 8 + tig + 4]);
            }
#pragma unroll
            for (int ni = 0; ni < 8; ni++)
                mma_tf32(sf[ni], qf[kk][0], qf[kk][1], qf[kk][2], qf[kk][3],
                         bfr[ni][0], bfr[ni][1]);
        }

        // ---- causal mask (diagonal tiles only) ----
        if (kt >= 2 * qx) {
            const int cb = kt * 64 + tig * 2;
#pragma unroll
            for (int ni = 0; ni < 8; ni++) {
                const int c0 = cb + ni * 8, c1 = c0 + 1;
                if (c0 > row0g) sf[ni][0] = -1e30f;
                if (c1 > row0g) sf[ni][1] = -1e30f;
                if (c0 > row1g) sf[ni][2] = -1e30f;
                if (c1 > row1g) sf[ni][3] = -1e30f;
            }
        }

        // ---- online softmax ----
        float mx0 = -1e30f, mx1 = -1e30f;
#pragma unroll
        for (int ni = 0; ni < 8; ni++) {
            mx0 = fmaxf(mx0, fmaxf(sf[ni][0], sf[ni][1]));
            mx1 = fmaxf(mx1, fmaxf(sf[ni][2], sf[ni][3]));
        }
        mx0 = fmaxf(mx0, __shfl_xor_sync(0xffffffffu, mx0, 1));
        mx0 = fmaxf(mx0, __shfl_xor_sync(0xffffffffu, mx0, 2));
        mx1 = fmaxf(mx1, __shfl_xor_sync(0xffffffffu, mx1, 1));
        mx1 = fmaxf(mx1, __shfl_xor_sync(0xffffffffu, mx1, 2));

        const float mn0 = fmaxf(m0, mx0);
        const float mn1 = fmaxf(m1, mx1);
        const float corr0 = __expf(m0 - mn0);
        const float corr1 = __expf(m1 - mn1);
        m0 = mn0; m1 = mn1;

        float ls0 = 0.0f, ls1 = 0.0f;
#pragma unroll
        for (int ni = 0; ni < 8; ni++) {
            sf[ni][0] = __expf(sf[ni][0] - mn0); ls0 += sf[ni][0];
            sf[ni][1] = __expf(sf[ni][1] - mn0); ls0 += sf[ni][1];
            sf[ni][2] = __expf(sf[ni][2] - mn1); ls1 += sf[ni][2];
            sf[ni][3] = __expf(sf[ni][3] - mn1); ls1 += sf[ni][3];
        }
        ls0 += __shfl_xor_sync(0xffffffffu, ls0, 1);
        ls0 += __shfl_xor_sync(0xffffffffu, ls0, 2);
        ls1 += __shfl_xor_sync(0xffffffffu, ls1, 1);
        ls1 += __shfl_xor_sync(0xffffffffu, ls1, 2);
        l0 = l0 * corr0 + ls0;
        l1 = l1 * corr1 + ls1;

#pragma unroll
        for (int ni = 0; ni < 8; ni++) {
            of[ni][0] *= corr0; of[ni][1] *= corr0;
            of[ni][2] *= corr1; of[ni][3] *= corr1;
        }

        // ---- stage P (tf32) for A-operand re-fragmentation ----
#pragma unroll
        for (int ni = 0; ni < 8; ni++) {
            float2 p0 = { tf32r(sf[ni][0]), tf32r(sf[ni][1]) };
            float2 p1 = { tf32r(sf[ni][2]), tf32r(sf[ni][3]) };
            *(float2*)&Ps[lr0 * KSTR + ni * 8 + tig * 2] = p0;
            *(float2*)&Ps[lr1 * KSTR + ni * 8 + tig * 2] = p1;
        }
        __syncthreads();

        // ---- O += P V  (V[key][d], VSTR=72 -> conflict-free B-frags) ----
#pragma unroll
        for (int kk = 0; kk < 8; kk++) {
            uint32_t pa0 = __float_as_uint(Ps[lr0 * KSTR + kk * 8 + tig]);
            uint32_t pa1 = __float_as_uint(Ps[lr1 * KSTR + kk * 8 + tig]);
            uint32_t pa2 = __float_as_uint(Ps[lr0 * KSTR + kk * 8 + tig + 4]);
            uint32_t pa3 = __float_as_uint(Ps[lr1 * KSTR + kk * 8 + tig + 4]);
#pragma unroll
            for (int ni = 0; ni < 8; ni++) {
                uint32_t b0 = __float_as_uint(Vs[(kk * 8 + tig)     * VSTR + ni * 8 + gid]);
                uint32_t b1 = __float_as_uint(Vs[(kk * 8 + tig + 4) * VSTR + ni * 8 + gid]);
                mma_tf32(of[ni], pa0, pa1, pa2, pa3, b0, b1);
            }
        }
    }

    // ---- epilogue (tf32-rounded: consumed by cp.async GEMM) ----
    const float inv0 = 1.0f / l0;
    const float inv1 = 1.0f / l1;
    float* o0 = out + (size_t)(b * 2048 + row0g) * 1024 + h * 64;
    float* o1 = o0 + (size_t)8 * 1024;
#pragma unroll
    for (int ni = 0; ni < 8; ni++) {
        float2 v0 = { tf32r(of[ni][0] * inv0), tf32r(of[ni][1] * inv0) };
        float2 v1 = { tf32r(of[ni][2] * inv1), tf32r(of[ni][3] * inv1) };
        *(float2*)(o0 + ni * 8 + tig * 2) = v0;
        *(float2*)(o1 + ni * 8 + tig * 2) = v1;
    }
}

// ---------------------------------------------------------------------------
// kernel_launch
// ---------------------------------------------------------------------------
extern "C" void kernel_launch(void* const* d_in, const int* in_sizes, int n_in,
                              void* d_out, int out_size)
{
    const float* x     = (const float*)d_in[0];   // [4096, 1024]
    const float* w_qkv = (const float*)d_in[1];   // [1024, 3072]
    const float* b_qkv = (const float*)d_in[2];   // [3072]
    const float* w_out = (const float*)d_in[3];   // [1024, 1024]
    const float* b_out = (const float*)d_in[4];   // [1024]
    float* out = (float*)d_out;                   // [4096, 1024]

    float *qkv = nullptr, *attn = nullptr, *wt = nullptr, *xr = nullptr;
    cudaGetSymbolAddress((void**)&qkv,  g_qkv);
    cudaGetSymbolAddress((void**)&attn, g_attn);
    cudaGetSymbolAddress((void**)&wt,   g_wt);
    cudaGetSymbolAddress((void**)&xr,   g_xr);
    float* wt_qkv = wt;                      // [3072, 1024]
    float* wt_out = wt + 3072 * 1024;        // [1024, 1024]

    cudaFuncSetAttribute(gemm_mma_kernel,
                         cudaFuncAttributeMaxDynamicSharedMemorySize, GEMM_SMEM);
    cudaFuncSetAttribute(flash_mma_kernel,
                         cudaFuncAttributeMaxDynamicSharedMemorySize, FL5_SMEM);

    // 0) pre-round x; transpose+round weights
    round_tf32_kernel<<<4096, 256>>>(x, xr, 4096 * 1024);
    {
        dim3 blk(32, 8);
        transpose_kernel<<<dim3(3072 / 32, 1024 / 32), blk>>>(w_qkv, wt_qkv, 1024, 3072);
        transpose_kernel<<<dim3(1024 / 32, 1024 / 32), blk>>>(w_out, wt_out, 1024, 1024);
    }

    // 1) QKV projection (tf32-rounded output for flash)
    {
        dim3 grid(3072 / 128, 4096 / 128);
        gemm_mma_kernel<<<grid, 256, GEMM_SMEM>>>(xr, wt_qkv, b_qkv, qkv, 4096, 3072, 1024, 1);
    }

    // 2) Causal flash attention -> g_attn (tf32-rounded)
    {
        dim3 grid(16, 2 * 16);
        flash_mma_kernel<<<grid, 256, FL5_SMEM>>>(qkv, attn);
    }

    // 3) Output projection (full-precision output)
    {
        dim3 grid(1024 / 128, 4096 / 128);
        gemm_mma_kernel<<<grid, 256, GEMM_SMEM>>>(attn, wt_out, b_out, out, 4096, 1024, 1024, 0);
    }
}

// round 14
// speedup vs baseline: 1.3097x; 1.0088x over previous
#include <cuda_runtime.h>
#include <cstdint>

// Problem constants: B=2, T=2048, C=1024, H=16, D=64
__device__ float g_qkv[4096 * 3072];
__device__ float g_attn[4096 * 1024];
__device__ float g_wt[3072 * 1024 + 1024 * 1024];   // W_qkv^T then W_out^T (tf32)
__device__ float g_xr[4096 * 1024];                 // x rounded to tf32

// ---------------------------------------------------------------------------
// helpers
// ---------------------------------------------------------------------------
static __device__ __forceinline__ uint32_t f2tf32(float f) {
    uint32_t u;
    asm("cvt.rna.tf32.f32 %0, %1;" : "=r"(u) : "f"(f));
    return u;
}
static __device__ __forceinline__ float tf32r(float f) {
    return __uint_as_float(f2tf32(f));
}
static __device__ __forceinline__ void mma_tf32(
    float c[4], uint32_t a0, uint32_t a1, uint32_t a2, uint32_t a3,
    uint32_t b0, uint32_t b1)
{
    asm volatile(
        "mma.sync.aligned.m16n8k8.row.col.f32.tf32.tf32.f32 "
        "{%0,%1,%2,%3}, {%4,%5,%6,%7}, {%8,%9}, {%0,%1,%2,%3};"
        : "+f"(c[0]), "+f"(c[1]), "+f"(c[2]), "+f"(c[3])
        : "r"(a0), "r"(a1), "r"(a2), "r"(a3), "r"(b0), "r"(b1));
}
static __device__ __forceinline__ uint32_t smem_u32(const void* p) {
    uint32_t a;
    asm("{ .reg .u64 t; cvta.to.shared.u64 t, %1; cvt.u32.u64 %0, t; }"
        : "=r"(a) : "l"(p));
    return a;
}
static __device__ __forceinline__ void cp16(uint32_t dst, const void* src) {
    asm volatile("cp.async.cg.shared.global [%0], [%1], 16;" :: "r"(dst), "l"(src));
}
#define CP_COMMIT() asm volatile("cp.async.commit_group;" ::: "memory")
#define CP_WAIT0()  asm volatile("cp.async.wait_group 0;" ::: "memory")
#define CP_WAIT1()  asm volatile("cp.async.wait_group 1;" ::: "memory")

// ---------------------------------------------------------------------------
// Elementwise tf32 rounding: out[i] = tf32(in[i])
// ---------------------------------------------------------------------------
__global__ void round_tf32_kernel(const float* __restrict__ in, float* __restrict__ out, int n)
{
    int i = (blockIdx.x * blockDim.x + threadIdx.x) * 4;
    if (i < n) {
        float4 v = *(const float4*)(in + i);
        float4 r = { tf32r(v.x), tf32r(v.y), tf32r(v.z), tf32r(v.w) };
        *(float4*)(out + i) = r;
    }
}

// ---------------------------------------------------------------------------
// Transpose + tf32 round: out[N,K] = tf32(in[K,N]).
// ---------------------------------------------------------------------------
__global__ void transpose_kernel(const float* __restrict__ in, float* __restrict__ out,
                                 int R, int Ccols)
{
    __shared__ float tile[32][33];
    int c = blockIdx.x * 32 + threadIdx.x;
    int r0 = blockIdx.y * 32;
#pragma unroll
    for (int i = 0; i < 32; i += 8)
        tile[threadIdx.y + i][threadIdx.x] =
            tf32r(in[(size_t)(r0 + threadIdx.y + i) * Ccols + c]);
    __syncthreads();
    int oc = blockIdx.y * 32 + threadIdx.x;
    int or0 = blockIdx.x * 32;
#pragma unroll
    for (int i = 0; i < 32; i += 8)
        out[(size_t)(or0 + threadIdx.y + i) * R + oc] = tile[threadIdx.x][threadIdx.y + i];
}

// ---------------------------------------------------------------------------
// mma.sync tf32 GEMM, 3-stage cp.async pipeline, coalesced loader.
// A, BT must be PRE-ROUNDED to tf32. round_out=1 -> tf32-rounded output.
// ---------------------------------------------------------------------------
constexpr int ASTR = 36;
constexpr int GEMM_SMEM = 3 * 2 * 128 * ASTR * (int)sizeof(float);   // 110592

__global__ __launch_bounds__(256)
void gemm_mma_kernel(const float* __restrict__ A, const float* __restrict__ BT,
                     const float* __restrict__ bias, float* __restrict__ C,
                     int M, int N, int K, int round_out)
{
    extern __shared__ float sm[];
    float* AsBase = sm;                      // [3][128][ASTR]
    float* BsBase = sm + 3 * 128 * ASTR;     // [3][128][ASTR]
    const uint32_t smem0 = smem_u32(sm);

    const int tid  = threadIdx.x;
    const int wid  = tid >> 5;
    const int lane = tid & 31;
    const int gid  = lane >> 2;
    const int tig  = lane & 3;
    const int warp_m = wid & 1;
    const int warp_n = wid >> 1;

    const int row0 = blockIdx.y * 128;
    const int n0   = blockIdx.x * 128;

    // coalesced cp.async mapping: 8 threads/row, 16B each; 4 row-groups of 32
    const int arow = tid >> 3;               // 0..31
    const int acol = (tid & 7) * 4;          // float offset 0..28
    const float* Ab = A  + (size_t)(row0 + arow) * K + acol;
    const float* Bb = BT + (size_t)(n0  + arow) * K + acol;
    const uint32_t adst0 = smem0 + (uint32_t)(arow * ASTR + acol) * 4;
    const uint32_t bdst0 = adst0 + (uint32_t)(3 * 128 * ASTR) * 4;
    const uint32_t rstep = (uint32_t)(32 * ASTR) * 4;    // 32 smem rows
    const uint32_t bufstep = (uint32_t)(128 * ASTR) * 4;

    float acc[4][4][4];
#pragma unroll
    for (int mi = 0; mi < 4; mi++)
#pragma unroll
        for (int ni = 0; ni < 4; ni++)
#pragma unroll
            for (int r = 0; r < 4; r++) acc[mi][ni][r] = 0.0f;

    const int nchunk = K / 32;

    // prologue: issue chunks 0 and 1 into buffers 0 and 1
#pragma unroll
    for (int p = 0; p < 2; p++) {
        const float* as = Ab + (size_t)p * 32;
        const float* bs = Bb + (size_t)p * 32;
        const uint32_t ad = adst0 + p * bufstep;
        const uint32_t bd = bdst0 + p * bufstep;
#pragma unroll
        for (int it = 0; it < 4; it++) {
            cp16(ad + it * rstep, as + (size_t)(it * 32) * K);
            cp16(bd + it * rstep, bs + (size_t)(it * 32) * K);
        }
        CP_COMMIT();
    }

    int buf = 0;
    for (int c = 0; c < nchunk; c++) {
        const float* As = AsBase + buf * 128 * ASTR;
        const float* Bs = BsBase + buf * 128 * ASTR;

        if (c + 1 < nchunk) CP_WAIT1(); else CP_WAIT0();
        __syncthreads();   // chunk c visible; compute on buf (c+2)%3 finished

        if (c + 2 < nchunk) {
            const int nb = (buf + 2) % 3;
            const float* as = Ab + (size_t)(c + 2) * 32;
            const float* bs = Bb + (size_t)(c + 2) * 32;
            const uint32_t ad = adst0 + nb * bufstep;
            const uint32_t bd = bdst0 + nb * bufstep;
#pragma unroll
            for (int it = 0; it < 4; it++) {
                cp16(ad + it * rstep, as + (size_t)(it * 32) * K);
                cp16(bd + it * rstep, bs + (size_t)(it * 32) * K);
            }
            CP_COMMIT();
        }

        const int mbase = warp_m * 64;
        const int nbase = warp_n * 32;
#pragma unroll
        for (int kk = 0; kk < 32; kk += 8) {
            uint32_t afr[4][4];
#pragma unroll
            for (int mi = 0; mi < 4; mi++) {
                const int r = mbase + mi * 16;
                afr[mi][0] = __float_as_uint(As[(r + gid)     * ASTR + kk + tig]);
                afr[mi][1] = __float_as_uint(As[(r + gid + 8) * ASTR + kk + tig]);
                afr[mi][2] = __float_as_uint(As[(r + gid)     * ASTR + kk + tig + 4]);
                afr[mi][3] = __float_as_uint(As[(r + gid + 8) * ASTR + kk + tig + 4]);
            }
            uint32_t bfr[4][2];
#pragma unroll
            for (int ni = 0; ni < 4; ni++) {
                const int n = nbase + ni * 8 + gid;
                bfr[ni][0] = __float_as_uint(Bs[n * ASTR + kk + tig]);
                bfr[ni][1] = __float_as_uint(Bs[n * ASTR + kk + tig + 4]);
            }
#pragma unroll
            for (int mi = 0; mi < 4; mi++)
#pragma unroll
                for (int ni = 0; ni < 4; ni++)
                    mma_tf32(acc[mi][ni], afr[mi][0], afr[mi][1], afr[mi][2], afr[mi][3],
                             bfr[ni][0], bfr[ni][1]);
        }

        buf = (buf + 1) % 3;
    }

#pragma unroll
    for (int mi = 0; mi < 4; mi++) {
        const int r = row0 + warp_m * 64 + mi * 16 + gid;
#pragma unroll
        for (int ni = 0; ni < 4; ni++) {
            const int cc = n0 + warp_n * 32 + ni * 8 + tig * 2;
            const float b0 = bias[cc], b1 = bias[cc + 1];
            float2 v0, v1;
            if (round_out) {
                v0 = make_float2(tf32r(acc[mi][ni][0] + b0), tf32r(acc[mi][ni][1] + b1));
                v1 = make_float2(tf32r(acc[mi][ni][2] + b0), tf32r(acc[mi][ni][3] + b1));
            } else {
                v0 = make_float2(acc[mi][ni][0] + b0, acc[mi][ni][1] + b1);
                v1 = make_float2(acc[mi][ni][2] + b0, acc[mi][ni][3] + b1);
            }
            *(float2*)(C + (size_t)r * N + cc)       = v0;
            *(float2*)(C + (size_t)(r + 8) * N + cc) = v1;
        }
    }
}

// ---------------------------------------------------------------------------
// Flash attention (causal), mma.sync tf32 (unchanged from R13).
// ---------------------------------------------------------------------------
constexpr int KSTR = 68;
constexpr int VSTR = 72;
constexpr int FL5_SMEM = (2 * 64 * KSTR + 2 * 64 * VSTR + 128 * KSTR) * (int)sizeof(float); // 106496

__global__ __launch_bounds__(256, 2)
void flash_mma_kernel(const float* __restrict__ qkv, float* __restrict__ out)
{
    extern __shared__ float sm[];
    float* KBuf = sm;                        // [2][64][KSTR]
    float* VBuf = sm + 2 * 64 * KSTR;        // [2][64][VSTR]
    float* Ps   = VBuf + 2 * 64 * VSTR;      // [128][KSTR]
    const uint32_t smem0 = smem_u32(sm);
    const uint32_t voff  = (uint32_t)(2 * 64 * KSTR) * 4;

    const int tid  = threadIdx.x;
    const int wid  = tid >> 5;
    const int lane = tid & 31;
    const int gid  = lane >> 2;
    const int tig  = lane & 3;

    const int qx = 15 - blockIdx.x;          // heavy tiles first
    const int bh = blockIdx.y;
    const int b  = bh >> 4;
    const int h  = bh & 15;
    const int q0 = qx * 128;
    const int rs = 3072;
    const float* base = qkv + (size_t)(b * 2048) * rs + h * 64;

    // coalesced cp.async mapping: 16 threads/row (16B each), 4 row-groups of 16
    const int ckey = tid >> 4;               // 0..15
    const int c16f = (tid & 15) * 4;         // float offset 0..60
    const int nkt  = 2 * qx + 2;

    // issue K/V tile 0 into buffer 0
#pragma unroll
    for (int it = 0; it < 4; it++) {
        const int key = ckey + it * 16;
        const float* ksrc = base + (size_t)key * rs + 1024 + c16f;
        cp16(smem0 + (uint32_t)(key * KSTR + c16f) * 4, ksrc);
        cp16(smem0 + voff + (uint32_t)(key * VSTR + c16f) * 4, ksrc + 1024);
    }
    CP_COMMIT();

    // ---- stage Q tile (exact x0.125; qkv already tf32) ----
#pragma unroll
    for (int i = 0; i < 8; i++) {
        int idx = tid + i * 256;
        int row = idx >> 4;
        int dg  = (idx & 15) * 4;
        float4 v = *(const float4*)(base + (size_t)(q0 + row) * rs + dg);
        float* d = &Ps[row * KSTR + dg];
        d[0] = v.x * 0.125f; d[1] = v.y * 0.125f;
        d[2] = v.z * 0.125f; d[3] = v.w * 0.125f;
    }
    __syncthreads();

    const int lr0 = wid * 16 + gid;
    const int lr1 = lr0 + 8;
    uint32_t qf[8][4];
#pragma unroll
    for (int kk = 0; kk < 8; kk++) {
        qf[kk][0] = __float_as_uint(Ps[lr0 * KSTR + kk * 8 + tig]);
        qf[kk][1] = __float_as_uint(Ps[lr1 * KSTR + kk * 8 + tig]);
        qf[kk][2] = __float_as_uint(Ps[lr0 * KSTR + kk * 8 + tig + 4]);
        qf[kk][3] = __float_as_uint(Ps[lr1 * KSTR + kk * 8 + tig + 4]);
    }

    float of[8][4];
#pragma unroll
    for (int ni = 0; ni < 8; ni++)
#pragma unroll
        for (int r = 0; r < 4; r++) of[ni][r] = 0.0f;
    float m0 = -1e30f, m1 = -1e30f, l0 = 0.0f, l1 = 0.0f;

    const int row0g = q0 + lr0;
    const int row1g = row0g + 8;

    for (int kt = 0; kt < nkt; kt++) {
        const int buf = kt & 1;
        const float* Ks = KBuf + buf * 64 * KSTR;
        const float* Vs = VBuf + buf * 64 * VSTR;

        CP_WAIT0();
        __syncthreads();

        if (kt + 1 < nkt) {
            const int kb = (buf ^ 1) * 64;
#pragma unroll
            for (int it = 0; it < 4; it++) {
                const int key = ckey + it * 16;
                const float* ksrc = base + (size_t)((kt + 1) * 64 + key) * rs + 1024 + c16f;
                cp16(smem0 + (uint32_t)((kb + key) * KSTR + c16f) * 4, ksrc);
                cp16(smem0 + voff + (uint32_t)((kb + key) * VSTR + c16f) * 4, ksrc + 1024);
            }
            CP_COMMIT();
        }

        // ---- S = Q K^T ----
        float sf[8][4];
#pragma unroll
        for (int ni = 0; ni < 8; ni++)
#pragma unroll
            for (int r = 0; r < 4; r++) sf[ni][r] = 0.0f;

#pragma unroll
        for (int kk = 0; kk < 8; kk++) {
            uint32_t bfr[8][2];
#pragma unroll
            for (int ni = 0; ni < 8; ni++) {
                bfr[ni][0] = __float_as_uint(Ks[(ni * 8 + gid) * KSTR + kk * 8 + tig]);
                bfr[ni][1] = __float_as_uint(Ks[(ni * 8 + gid) * KSTR + kk * 8 + tig + 4]);
            }
#pragma unroll
            for (int ni = 0; ni < 8; ni++)
                mma_tf32(sf[ni], qf[kk][0], qf[kk][1], qf[kk][2], qf[kk][3],
                         bfr[ni][0], bfr[ni][1]);
        }

        // ---- causal mask (diagonal tiles only) ----
        if (kt >= 2 * qx) {
            const int cb = kt * 64 + tig * 2;
#pragma unroll
            for (int ni = 0; ni < 8; ni++) {
                const int c0 = cb + ni * 8, c1 = c0 + 1;
                if (c0 > row0g) sf[ni][0] = -1e30f;
                if (c1 > row0g) sf[ni][1] = -1e30f;
                if (c0 > row1g) sf[ni][2] = -1e30f;
                if (c1 > row1g) sf[ni][3] = -1e30f;
            }
        }

        // ---- online softmax ----
        float mx0 = -1e30f, mx1 = -1e30f;
#pragma unroll
        for (int ni = 0; ni < 8; ni++) {
            mx0 = fmaxf(mx0, fmaxf(sf[ni][0], sf[ni][1]));
            mx1 = fmaxf(mx1, fmaxf(sf[ni][2], sf[ni][3]));
        }
        mx0 = fmaxf(mx0, __shfl_xor_sync(0xffffffffu, mx0, 1));
        mx0 = fmaxf(mx0, __shfl_xor_sync(0xffffffffu, mx0, 2));
        mx1 = fmaxf(mx1, __shfl_xor_sync(0xffffffffu, mx1, 1));
        mx1 = fmaxf(mx1, __shfl_xor_sync(0xffffffffu, mx1, 2));

        const float mn0 = fmaxf(m0, mx0);
        const float mn1 = fmaxf(m1, mx1);
        const float corr0 = __expf(m0 - mn0);
        const float corr1 = __expf(m1 - mn1);
        m0 = mn0; m1 = mn1;

        float ls0 = 0.0f, ls1 = 0.0f;
#pragma unroll
        for (int ni = 0; ni < 8; ni++) {
            sf[ni][0] = __expf(sf[ni][0] - mn0); ls0 += sf[ni][0];
            sf[ni][1] = __expf(sf[ni][1] - mn0); ls0 += sf[ni][1];
            sf[ni][2] = __expf(sf[ni][2] - mn1); ls1 += sf[ni][2];
            sf[ni][3] = __expf(sf[ni][3] - mn1); ls1 += sf[ni][3];
        }
        ls0 += __shfl_xor_sync(0xffffffffu, ls0, 1);
        ls0 += __shfl_xor_sync(0xffffffffu, ls0, 2);
        ls1 += __shfl_xor_sync(0xffffffffu, ls1, 1);
        ls1 += __shfl_xor_sync(0xffffffffu, ls1, 2);
        l0 = l0 * corr0 + ls0;
        l1 = l1 * corr1 + ls1;

#pragma unroll
        for (int ni = 0; ni < 8; ni++) {
            of[ni][0] *= corr0; of[ni][1] *= corr0;
            of[ni][2] *= corr1; of[ni][3] *= corr1;
        }

        // ---- stage P (tf32) for A-operand re-fragmentation ----
#pragma unroll
        for (int ni = 0; ni < 8; ni++) {
            float2 p0 = { tf32r(sf[ni][0]), tf32r(sf[ni][1]) };
            float2 p1 = { tf32r(sf[ni][2]), tf32r(sf[ni][3]) };
            *(float2*)&Ps[lr0 * KSTR + ni * 8 + tig * 2] = p0;
            *(float2*)&Ps[lr1 * KSTR + ni * 8 + tig * 2] = p1;
        }
        __syncthreads();

        // ---- O += P V  (V[key][d], VSTR=72 -> conflict-free B-frags) ----
#pragma unroll
        for (int kk = 0; kk < 8; kk++) {
            uint32_t pa0 = __float_as_uint(Ps[lr0 * KSTR + kk * 8 + tig]);
            uint32_t pa1 = __float_as_uint(Ps[lr1 * KSTR + kk * 8 + tig]);
            uint32_t pa2 = __float_as_uint(Ps[lr0 * KSTR + kk * 8 + tig + 4]);
            uint32_t pa3 = __float_as_uint(Ps[lr1 * KSTR + kk * 8 + tig + 4]);
#pragma unroll
            for (int ni = 0; ni < 8; ni++) {
                uint32_t b0 = __float_as_uint(Vs[(kk * 8 + tig)     * VSTR + ni * 8 + gid]);
                uint32_t b1 = __float_as_uint(Vs[(kk * 8 + tig + 4) * VSTR + ni * 8 + gid]);
                mma_tf32(of[ni], pa0, pa1, pa2, pa3, b0, b1);
            }
        }
    }

    // ---- epilogue (tf32-rounded: consumed by cp.async GEMM) ----
    const float inv0 = 1.0f / l0;
    const float inv1 = 1.0f / l1;
    float* o0 = out + (size_t)(b * 2048 + row0g) * 1024 + h * 64;
    float* o1 = o0 + (size_t)8 * 1024;
#pragma unroll
    for (int ni = 0; ni < 8; ni++) {
        float2 v0 = { tf32r(of[ni][0] * inv0), tf32r(of[ni][1] * inv0) };
        float2 v1 = { tf32r(of[ni][2] * inv1), tf32r(of[ni][3] * inv1) };
        *(float2*)(o0 + ni * 8 + tig * 2) = v0;
        *(float2*)(o1 + ni * 8 + tig * 2) = v1;
    }
}

// ---------------------------------------------------------------------------
// kernel_launch
// ---------------------------------------------------------------------------
extern "C" void kernel_launch(void* const* d_in, const int* in_sizes, int n_in,
                              void* d_out, int out_size)
{
    const float* x     = (const float*)d_in[0];   // [4096, 1024]
    const float* w_qkv = (const float*)d_in[1];   // [1024, 3072]
    const float* b_qkv = (const float*)d_in[2];   // [3072]
    const float* w_out = (const float*)d_in[3];   // [1024, 1024]
    const float* b_out = (const float*)d_in[4];   // [1024]
    float* out = (float*)d_out;                   // [4096, 1024]

    float *qkv = nullptr, *attn = nullptr, *wt = nullptr, *xr = nullptr;
    cudaGetSymbolAddress((void**)&qkv,  g_qkv);
    cudaGetSymbolAddress((void**)&attn, g_attn);
    cudaGetSymbolAddress((void**)&wt,   g_wt);
    cudaGetSymbolAddress((void**)&xr,   g_xr);
    float* wt_qkv = wt;                      // [3072, 1024]
    float* wt_out = wt + 3072 * 1024;        // [1024, 1024]

    cudaFuncSetAttribute(gemm_mma_kernel,
                         cudaFuncAttributeMaxDynamicSharedMemorySize, GEMM_SMEM);
    cudaFuncSetAttribute(flash_mma_kernel,
                         cudaFuncAttributeMaxDynamicSharedMemorySize, FL5_SMEM);

    // 0) pre-round x; transpose+round weights
    round_tf32_kernel<<<4096, 256>>>(x, xr, 4096 * 1024);
    {
        dim3 blk(32, 8);
        transpose_kernel<<<dim3(3072 / 32, 1024 / 32), blk>>>(w_qkv, wt_qkv, 1024, 3072);
        transpose_kernel<<<dim3(1024 / 32, 1024 / 32), blk>>>(w_out, wt_out, 1024, 1024);
    }

    // 1) QKV projection (tf32-rounded output for flash)
    {
        dim3 grid(3072 / 128, 4096 / 128);
        gemm_mma_kernel<<<grid, 256, GEMM_SMEM>>>(xr, wt_qkv, b_qkv, qkv, 4096, 3072, 1024, 1);
    }

    // 2) Causal flash attention -> g_attn (tf32-rounded)
    {
        dim3 grid(16, 2 * 16);
        flash_mma_kernel<<<grid, 256, FL5_SMEM>>>(qkv, attn);
    }

    // 3) Output projection (full-precision output)
    {
        dim3 grid(1024 / 128, 4096 / 128);
        gemm_mma_kernel<<<grid, 256, GEMM_SMEM>>>(attn, wt_out, b_out, out, 4096, 1024, 1024, 0);
    }
}

// round 15
// speedup vs baseline: 1.3529x; 1.0330x over previous
#include <cuda_runtime.h>
#include <cstdint>

// Problem constants: B=2, T=2048, C=1024, H=16, D=64
__device__ float g_qkv[4096 * 3072];
__device__ float g_attn[4096 * 1024];
__device__ float g_wt[3072 * 1024 + 1024 * 1024];   // W_qkv^T then W_out^T (tf32, K-permuted)
__device__ float g_xr[4096 * 1024];                 // x rounded to tf32, K-permuted

// K-permutation within 8-blocks: source col j -> position (j<4 ? 2j : 2(j-4)+1).
// Applied identically to both GEMM operands' contraction dims -> results unchanged.

// ---------------------------------------------------------------------------
// helpers
// ---------------------------------------------------------------------------
static __device__ __forceinline__ uint32_t f2tf32(float f) {
    uint32_t u;
    asm("cvt.rna.tf32.f32 %0, %1;" : "=r"(u) : "f"(f));
    return u;
}
static __device__ __forceinline__ float tf32r(float f) {
    return __uint_as_float(f2tf32(f));
}
static __device__ __forceinline__ void mma_tf32(
    float c[4], uint32_t a0, uint32_t a1, uint32_t a2, uint32_t a3,
    uint32_t b0, uint32_t b1)
{
    asm volatile(
        "mma.sync.aligned.m16n8k8.row.col.f32.tf32.tf32.f32 "
        "{%0,%1,%2,%3}, {%4,%5,%6,%7}, {%8,%9}, {%0,%1,%2,%3};"
        : "+f"(c[0]), "+f"(c[1]), "+f"(c[2]), "+f"(c[3])
        : "r"(a0), "r"(a1), "r"(a2), "r"(a3), "r"(b0), "r"(b1));
}
static __device__ __forceinline__ uint32_t smem_u32(const void* p) {
    uint32_t a;
    asm("{ .reg .u64 t; cvta.to.shared.u64 t, %1; cvt.u32.u64 %0, t; }"
        : "=r"(a) : "l"(p));
    return a;
}
static __device__ __forceinline__ void cp16(uint32_t dst, const void* src) {
    asm volatile("cp.async.cg.shared.global [%0], [%1], 16;" :: "r"(dst), "l"(src));
}
#define CP_COMMIT() asm volatile("cp.async.commit_group;" ::: "memory")
#define CP_WAIT0()  asm volatile("cp.async.wait_group 0;" ::: "memory")

// ---------------------------------------------------------------------------
// Round to tf32 + permute columns within 8-blocks. Each thread owns one 8-block.
// ---------------------------------------------------------------------------
__global__ void round_perm_kernel(const float* __restrict__ in, float* __restrict__ out, int n)
{
    int base = (blockIdx.x * blockDim.x + threadIdx.x) * 8;
    if (base < n) {
        float4 v0 = *(const float4*)(in + base);
        float4 v1 = *(const float4*)(in + base + 4);
        out[base + 0] = tf32r(v0.x);
        out[base + 2] = tf32r(v0.y);
        out[base + 4] = tf32r(v0.z);
        out[base + 6] = tf32r(v0.w);
        out[base + 1] = tf32r(v1.x);
        out[base + 3] = tf32r(v1.y);
        out[base + 5] = tf32r(v1.z);
        out[base + 7] = tf32r(v1.w);
    }
}

// ---------------------------------------------------------------------------
// Transpose + tf32 round + K-permute: out[N,K] = tf32(in[K,N]), K permuted.
// ---------------------------------------------------------------------------
__global__ void transpose_kernel(const float* __restrict__ in, float* __restrict__ out,
                                 int R, int Ccols)
{
    __shared__ float tile[32][33];
    int c = blockIdx.x * 32 + threadIdx.x;
    int r0 = blockIdx.y * 32;
#pragma unroll
    for (int i = 0; i < 32; i += 8)
        tile[threadIdx.y + i][threadIdx.x] =
            tf32r(in[(size_t)(r0 + threadIdx.y + i) * Ccols + c]);
    __syncthreads();
    int oc = blockIdx.y * 32 + threadIdx.x;       // K index
    int j  = oc & 7;
    int ocp = (oc & ~7) + ((j < 4) ? (2 * j) : (2 * (j - 4) + 1));
    int or0 = blockIdx.x * 32;
#pragma unroll
    for (int i = 0; i < 32; i += 8)
        out[(size_t)(or0 + threadIdx.y + i) * R + ocp] = tile[threadIdx.x][threadIdx.y + i];
}

// ---------------------------------------------------------------------------
// mma.sync tf32 GEMM, 2-stage cp.async, K-PERMUTED operands:
// fragment (tig, tig+4) pairs sit at adjacent positions (2tig, 2tig+1)
// -> one LDS.64 each. ASTR=40 makes all fragment loads conflict-free.
// A, BT pre-rounded tf32 and K-permuted. round_out=1 -> tf32-rounded output.
// ---------------------------------------------------------------------------
constexpr int ASTR = 40;
constexpr int GEMM_SMEM = 2 * 2 * 128 * ASTR * (int)sizeof(float);   // 81920

__global__ __launch_bounds__(256)
void gemm_mma_kernel(const float* __restrict__ A, const float* __restrict__ BT,
                     const float* __restrict__ bias, float* __restrict__ C,
                     int M, int N, int K, int round_out)
{
    extern __shared__ float sm[];
    float* AsBase = sm;                      // [2][128][ASTR]
    float* BsBase = sm + 2 * 128 * ASTR;     // [2][128][ASTR]
    const uint32_t smem0 = smem_u32(sm);

    const int tid  = threadIdx.x;
    const int wid  = tid >> 5;
    const int lane = tid & 31;
    const int gid  = lane >> 2;
    const int tig  = lane & 3;
    const int warp_m = wid & 1;
    const int warp_n = wid >> 1;

    const int row0 = blockIdx.y * 128;
    const int n0   = blockIdx.x * 128;

    // coalesced cp.async mapping: 8 threads/row, 16B each; 4 row-groups of 32
    const int arow = tid >> 3;               // 0..31
    const int acol = (tid & 7) * 4;          // float offset 0..28
    const float* Ab = A  + (size_t)(row0 + arow) * K + acol;
    const float* Bb = BT + (size_t)(n0  + arow) * K + acol;
    const uint32_t adst0 = smem0 + (uint32_t)(arow * ASTR + acol) * 4;
    const uint32_t bdst0 = adst0 + (uint32_t)(2 * 128 * ASTR) * 4;
    const uint32_t rstep = (uint32_t)(32 * ASTR) * 4;
    const uint32_t bufstep = (uint32_t)(128 * ASTR) * 4;

    float acc[4][4][4];
#pragma unroll
    for (int mi = 0; mi < 4; mi++)
#pragma unroll
        for (int ni = 0; ni < 4; ni++)
#pragma unroll
            for (int r = 0; r < 4; r++) acc[mi][ni][r] = 0.0f;

    const int nchunk = K / 32;

    // prologue: issue chunk 0 into buffer 0
#pragma unroll
    for (int it = 0; it < 4; it++) {
        cp16(adst0 + it * rstep, Ab + (size_t)(it * 32) * K);
        cp16(bdst0 + it * rstep, Bb + (size_t)(it * 32) * K);
    }
    CP_COMMIT();

    for (int c = 0; c < nchunk; c++) {
        const int buf = c & 1;
        const float* As = AsBase + buf * 128 * ASTR;
        const float* Bs = BsBase + buf * 128 * ASTR;

        CP_WAIT0();
        __syncthreads();

        if (c + 1 < nchunk) {
            const float* as = Ab + (size_t)(c + 1) * 32;
            const float* bs = Bb + (size_t)(c + 1) * 32;
            const uint32_t ad = adst0 + (buf ^ 1) * bufstep;
            const uint32_t bd = bdst0 + (buf ^ 1) * bufstep;
#pragma unroll
            for (int it = 0; it < 4; it++) {
                cp16(ad + it * rstep, as + (size_t)(it * 32) * K);
                cp16(bd + it * rstep, bs + (size_t)(it * 32) * K);
            }
            CP_COMMIT();
        }

        const int mbase = warp_m * 64;
        const int nbase = warp_n * 32;
#pragma unroll
        for (int kk = 0; kk < 32; kk += 8) {
            uint32_t afr[4][4];
#pragma unroll
            for (int mi = 0; mi < 4; mi++) {
                const int r = mbase + mi * 16;
                float2 alo = *(const float2*)&As[(r + gid)     * ASTR + kk + tig * 2];
                float2 ahi = *(const float2*)&As[(r + gid + 8) * ASTR + kk + tig * 2];
                afr[mi][0] = __float_as_uint(alo.x);
                afr[mi][1] = __float_as_uint(ahi.x);
                afr[mi][2] = __float_as_uint(alo.y);
                afr[mi][3] = __float_as_uint(ahi.y);
            }
            uint32_t bfr[4][2];
#pragma unroll
            for (int ni = 0; ni < 4; ni++) {
                const int n = nbase + ni * 8 + gid;
                float2 bv = *(const float2*)&Bs[n * ASTR + kk + tig * 2];
                bfr[ni][0] = __float_as_uint(bv.x);
                bfr[ni][1] = __float_as_uint(bv.y);
            }
#pragma unroll
            for (int mi = 0; mi < 4; mi++)
#pragma unroll
                for (int ni = 0; ni < 4; ni++)
                    mma_tf32(acc[mi][ni], afr[mi][0], afr[mi][1], afr[mi][2], afr[mi][3],
                             bfr[ni][0], bfr[ni][1]);
        }
    }

#pragma unroll
    for (int mi = 0; mi < 4; mi++) {
        const int r = row0 + warp_m * 64 + mi * 16 + gid;
#pragma unroll
        for (int ni = 0; ni < 4; ni++) {
            const int cc = n0 + warp_n * 32 + ni * 8 + tig * 2;
            const float b0 = bias[cc], b1 = bias[cc + 1];
            float2 v0, v1;
            if (round_out) {
                v0 = make_float2(tf32r(acc[mi][ni][0] + b0), tf32r(acc[mi][ni][1] + b1));
                v1 = make_float2(tf32r(acc[mi][ni][2] + b0), tf32r(acc[mi][ni][3] + b1));
            } else {
                v0 = make_float2(acc[mi][ni][0] + b0, acc[mi][ni][1] + b1);
                v1 = make_float2(acc[mi][ni][2] + b0, acc[mi][ni][3] + b1);
            }
            *(float2*)(C + (size_t)r * N + cc)       = v0;
            *(float2*)(C + (size_t)(r + 8) * N + cc) = v1;
        }
    }
}

// ---------------------------------------------------------------------------
// Flash attention (causal), mma.sync tf32 (R13/R14 core, unchanged except the
// epilogue writes attn with K-permuted columns for the out-proj GEMM).
// ---------------------------------------------------------------------------
constexpr int KSTR = 68;
constexpr int VSTR = 72;
constexpr int FL5_SMEM = (2 * 64 * KSTR + 2 * 64 * VSTR + 128 * KSTR) * (int)sizeof(float); // 106496

__global__ __launch_bounds__(256, 2)
void flash_mma_kernel(const float* __restrict__ qkv, float* __restrict__ out)
{
    extern __shared__ float sm[];
    float* KBuf = sm;                        // [2][64][KSTR]
    float* VBuf = sm + 2 * 64 * KSTR;        // [2][64][VSTR]
    float* Ps   = VBuf + 2 * 64 * VSTR;      // [128][KSTR]
    const uint32_t smem0 = smem_u32(sm);
    const uint32_t voff  = (uint32_t)(2 * 64 * KSTR) * 4;

    const int tid  = threadIdx.x;
    const int wid  = tid >> 5;
    const int lane = tid & 31;
    const int gid  = lane >> 2;
    const int tig  = lane & 3;

    const int qx = 15 - blockIdx.x;          // heavy tiles first
    const int bh = blockIdx.y;
    const int b  = bh >> 4;
    const int h  = bh & 15;
    const int q0 = qx * 128;
    const int rs = 3072;
    const float* base = qkv + (size_t)(b * 2048) * rs + h * 64;

    const int ckey = tid >> 4;               // 0..15
    const int c16f = (tid & 15) * 4;
    const int nkt  = 2 * qx + 2;

    // issue K/V tile 0 into buffer 0
#pragma unroll
    for (int it = 0; it < 4; it++) {
        const int key = ckey + it * 16;
        const float* ksrc = base + (size_t)key * rs + 1024 + c16f;
        cp16(smem0 + (uint32_t)(key * KSTR + c16f) * 4, ksrc);
        cp16(smem0 + voff + (uint32_t)(key * VSTR + c16f) * 4, ksrc + 1024);
    }
    CP_COMMIT();

    // ---- stage Q tile (exact x0.125; qkv already tf32) ----
#pragma unroll
    for (int i = 0; i < 8; i++) {
        int idx = tid + i * 256;
        int row = idx >> 4;
        int dg  = (idx & 15) * 4;
        float4 v = *(const float4*)(base + (size_t)(q0 + row) * rs + dg);
        float* d = &Ps[row * KSTR + dg];
        d[0] = v.x * 0.125f; d[1] = v.y * 0.125f;
        d[2] = v.z * 0.125f; d[3] = v.w * 0.125f;
    }
    __syncthreads();

    const int lr0 = wid * 16 + gid;
    const int lr1 = lr0 + 8;
    uint32_t qf[8][4];
#pragma unroll
    for (int kk = 0; kk < 8; kk++) {
        qf[kk][0] = __float_as_uint(Ps[lr0 * KSTR + kk * 8 + tig]);
        qf[kk][1] = __float_as_uint(Ps[lr1 * KSTR + kk * 8 + tig]);
        qf[kk][2] = __float_as_uint(Ps[lr0 * KSTR + kk * 8 + tig + 4]);
        qf[kk][3] = __float_as_uint(Ps[lr1 * KSTR + kk * 8 + tig + 4]);
    }

    float of[8][4];
#pragma unroll
    for (int ni = 0; ni < 8; ni++)
#pragma unroll
        for (int r = 0; r < 4; r++) of[ni][r] = 0.0f;
    float m0 = -1e30f, m1 = -1e30f, l0 = 0.0f, l1 = 0.0f;

    const int row0g = q0 + lr0;
    const int row1g = row0g + 8;

    for (int kt = 0; kt < nkt; kt++) {
        const int buf = kt & 1;
        const float* Ks = KBuf + buf * 64 * KSTR;
        const float* Vs = VBuf + buf * 64 * VSTR;

        CP_WAIT0();
        __syncthreads();

        if (kt + 1 < nkt) {
            const int kb = (buf ^ 1) * 64;
#pragma unroll
            for (int it = 0; it < 4; it++) {
                const int key = ckey + it * 16;
                const float* ksrc = base + (size_t)((kt + 1) * 64 + key) * rs + 1024 + c16f;
                cp16(smem0 + (uint32_t)((kb + key) * KSTR + c16f) * 4, ksrc);
                cp16(smem0 + voff + (uint32_t)((kb + key) * VSTR + c16f) * 4, ksrc + 1024);
            }
            CP_COMMIT();
        }

        // ---- S = Q K^T ----
        float sf[8][4];
#pragma unroll
        for (int ni = 0; ni < 8; ni++)
#pragma unroll
            for (int r = 0; r < 4; r++) sf[ni][r] = 0.0f;

#pragma unroll
        for (int kk = 0; kk < 8; kk++) {
            uint32_t bfr[8][2];
#pragma unroll
            for (int ni = 0; ni < 8; ni++) {
                bfr[ni][0] = __float_as_uint(Ks[(ni * 8 + gid) * KSTR + kk * 8 + tig]);
                bfr[ni][1] = __float_as_uint(Ks[(ni * 8 + gid) * KSTR + kk * 8 + tig + 4]);
            }
#pragma unroll
            for (int ni = 0; ni < 8; ni++)
                mma_tf32(sf[ni], qf[kk][0], qf[kk][1], qf[kk][2], qf[kk][3],
                         bfr[ni][0], bfr[ni][1]);
        }

        // ---- causal mask (diagonal tiles only) ----
        if (kt >= 2 * qx) {
            const int cb = kt * 64 + tig * 2;
#pragma unroll
            for (int ni = 0; ni < 8; ni++) {
                const int c0 = cb + ni * 8, c1 = c0 + 1;
                if (c0 > row0g) sf[ni][0] = -1e30f;
                if (c1 > row0g) sf[ni][1] = -1e30f;
                if (c0 > row1g) sf[ni][2] = -1e30f;
                if (c1 > row1g) sf[ni][3] = -1e30f;
            }
        }

        // ---- online softmax ----
        float mx0 = -1e30f, mx1 = -1e30f;
#pragma unroll
        for (int ni = 0; ni < 8; ni++) {
            mx0 = fmaxf(mx0, fmaxf(sf[ni][0], sf[ni][1]));
            mx1 = fmaxf(mx1, fmaxf(sf[ni][2], sf[ni][3]));
        }
        mx0 = fmaxf(mx0, __shfl_xor_sync(0xffffffffu, mx0, 1));
        mx0 = fmaxf(mx0, __shfl_xor_sync(0xffffffffu, mx0, 2));
        mx1 = fmaxf(mx1, __shfl_xor_sync(0xffffffffu, mx1, 1));
        mx1 = fmaxf(mx1, __shfl_xor_sync(0xffffffffu, mx1, 2));

        const float mn0 = fmaxf(m0, mx0);
        const float mn1 = fmaxf(m1, mx1);
        const float corr0 = __expf(m0 - mn0);
        const float corr1 = __expf(m1 - mn1);
        m0 = mn0; m1 = mn1;

        float ls0 = 0.0f, ls1 = 0.0f;
#pragma unroll
        for (int ni = 0; ni < 8; ni++) {
            sf[ni][0] = __expf(sf[ni][0] - mn0); ls0 += sf[ni][0];
            sf[ni][1] = __expf(sf[ni][1] - mn0); ls0 += sf[ni][1];
            sf[ni][2] = __expf(sf[ni][2] - mn1); ls1 += sf[ni][2];
            sf[ni][3] = __expf(sf[ni][3] - mn1); ls1 += sf[ni][3];
        }
        ls0 += __shfl_xor_sync(0xffffffffu, ls0, 1);
        ls0 += __shfl_xor_sync(0xffffffffu, ls0, 2);
        ls1 += __shfl_xor_sync(0xffffffffu, ls1, 1);
        ls1 += __shfl_xor_sync(0xffffffffu, ls1, 2);
        l0 = l0 * corr0 + ls0;
        l1 = l1 * corr1 + ls1;

#pragma unroll
        for (int ni = 0; ni < 8; ni++) {
            of[ni][0] *= corr0; of[ni][1] *= corr0;
            of[ni][2] *= corr1; of[ni][3] *= corr1;
        }

        // ---- stage P (tf32) for A-operand re-fragmentation ----
#pragma unroll
        for (int ni = 0; ni < 8; ni++) {
            float2 p0 = { tf32r(sf[ni][0]), tf32r(sf[ni][1]) };
            float2 p1 = { tf32r(sf[ni][2]), tf32r(sf[ni][3]) };
            *(float2*)&Ps[lr0 * KSTR + ni * 8 + tig * 2] = p0;
            *(float2*)&Ps[lr1 * KSTR + ni * 8 + tig * 2] = p1;
        }
        __syncthreads();

        // ---- O += P V  (V[key][d], VSTR=72 -> conflict-free B-frags) ----
#pragma unroll
        for (int kk = 0; kk < 8; kk++) {
            uint32_t pa0 = __float_as_uint(Ps[lr0 * KSTR + kk * 8 + tig]);
            uint32_t pa1 = __float_as_uint(Ps[lr1 * KSTR + kk * 8 + tig]);
            uint32_t pa2 = __float_as_uint(Ps[lr0 * KSTR + kk * 8 + tig + 4]);
            uint32_t pa3 = __float_as_uint(Ps[lr1 * KSTR + kk * 8 + tig + 4]);
#pragma unroll
            for (int ni = 0; ni < 8; ni++) {
                uint32_t b0 = __float_as_uint(Vs[(kk * 8 + tig)     * VSTR + ni * 8 + gid]);
                uint32_t b1 = __float_as_uint(Vs[(kk * 8 + tig + 4) * VSTR + ni * 8 + gid]);
                mma_tf32(of[ni], pa0, pa1, pa2, pa3, b0, b1);
            }
        }
    }

    // ---- epilogue: tf32-rounded, K-PERMUTED columns (for out-proj GEMM) ----
    const float inv0 = 1.0f / l0;
    const float inv1 = 1.0f / l1;
    float* o0 = out + (size_t)(b * 2048 + row0g) * 1024 + h * 64;
    float* o1 = o0 + (size_t)8 * 1024;
    // permuted positions of source cols 2tig and 2tig+1 within the 8-block
    const int pp0 = (tig < 2) ? (4 * tig)     : (4 * tig - 7);
    const int pp1 = (tig < 2) ? (4 * tig + 2) : (4 * tig - 5);
#pragma unroll
    for (int ni = 0; ni < 8; ni++) {
        o0[ni * 8 + pp0] = tf32r(of[ni][0] * inv0);
        o0[ni * 8 + pp1] = tf32r(of[ni][1] * inv0);
        o1[ni * 8 + pp0] = tf32r(of[ni][2] * inv1);
        o1[ni * 8 + pp1] = tf32r(of[ni][3] * inv1);
    }
}

// ---------------------------------------------------------------------------
// kernel_launch
// ---------------------------------------------------------------------------
extern "C" void kernel_launch(void* const* d_in, const int* in_sizes, int n_in,
                              void* d_out, int out_size)
{
    const float* x     = (const float*)d_in[0];   // [4096, 1024]
    const float* w_qkv = (const float*)d_in[1];   // [1024, 3072]
    const float* b_qkv = (const float*)d_in[2];   // [3072]
    const float* w_out = (const float*)d_in[3];   // [1024, 1024]
    const float* b_out = (const float*)d_in[4];   // [1024]
    float* out = (float*)d_out;                   // [4096, 1024]

    float *qkv = nullptr, *attn = nullptr, *wt = nullptr, *xr = nullptr;
    cudaGetSymbolAddress((void**)&qkv,  g_qkv);
    cudaGetSymbolAddress((void**)&attn, g_attn);
    cudaGetSymbolAddress((void**)&wt,   g_wt);
    cudaGetSymbolAddress((void**)&xr,   g_xr);
    float* wt_qkv = wt;                      // [3072, 1024]
    float* wt_out = wt + 3072 * 1024;        // [1024, 1024]

    cudaFuncSetAttribute(gemm_mma_kernel,
                         cudaFuncAttributeMaxDynamicSharedMemorySize, GEMM_SMEM);
    cudaFuncSetAttribute(flash_mma_kernel,
                         cudaFuncAttributeMaxDynamicSharedMemorySize, FL5_SMEM);

    // 0) pre-round + K-permute x; transpose + round + K-permute weights
    round_perm_kernel<<<2048, 256>>>(x, xr, 4096 * 1024);
    {
        dim3 blk(32, 8);
        transpose_kernel<<<dim3(3072 / 32, 1024 / 32), blk>>>(w_qkv, wt_qkv, 1024, 3072);
        transpose_kernel<<<dim3(1024 / 32, 1024 / 32), blk>>>(w_out, wt_out, 1024, 1024);
    }

    // 1) QKV projection (tf32-rounded output for flash)
    {
        dim3 grid(3072 / 128, 4096 / 128);
        gemm_mma_kernel<<<grid, 256, GEMM_SMEM>>>(xr, wt_qkv, b_qkv, qkv, 4096, 3072, 1024, 1);
    }

    // 2) Causal flash attention -> g_attn (tf32-rounded, K-permuted cols)
    {
        dim3 grid(16, 2 * 16);
        flash_mma_kernel<<<grid, 256, FL5_SMEM>>>(qkv, attn);
    }

    // 3) Output projection (full-precision output)
    {
        dim3 grid(1024 / 128, 4096 / 128);
        gemm_mma_kernel<<<grid, 256, GEMM_SMEM>>>(attn, wt_out, b_out, out, 4096, 1024, 1024, 0);
    }
}

// round 16
// speedup vs baseline: 1.3792x; 1.0194x over previous
#include <cuda_runtime.h>
#include <cstdint>

// Problem constants: B=2, T=2048, C=1024, H=16, D=64
__device__ float g_qkv[4096 * 3072];
__device__ float g_attn[4096 * 1024];
__device__ float g_wt[3072 * 1024 + 1024 * 1024];   // W_qkv^T then W_out^T (tf32, K-permuted)
__device__ float g_xr[4096 * 1024];                 // x rounded to tf32, K-permuted

// K-permutation within 8-blocks: source col j -> position (j<4 ? 2j : 2(j-4)+1).
// Applied to both operands of every contraction -> results unchanged.
// qkv is stored d-permuted; attn emerges d-permuted (V output dim), matching
// the K-permuted out-proj weights.

// ---------------------------------------------------------------------------
// helpers
// ---------------------------------------------------------------------------
static __device__ __forceinline__ uint32_t f2tf32(float f) {
    uint32_t u;
    asm("cvt.rna.tf32.f32 %0, %1;" : "=r"(u) : "f"(f));
    return u;
}
static __device__ __forceinline__ float tf32r(float f) {
    return __uint_as_float(f2tf32(f));
}
static __device__ __forceinline__ void mma_tf32(
    float c[4], uint32_t a0, uint32_t a1, uint32_t a2, uint32_t a3,
    uint32_t b0, uint32_t b1)
{
    asm volatile(
        "mma.sync.aligned.m16n8k8.row.col.f32.tf32.tf32.f32 "
        "{%0,%1,%2,%3}, {%4,%5,%6,%7}, {%8,%9}, {%0,%1,%2,%3};"
        : "+f"(c[0]), "+f"(c[1]), "+f"(c[2]), "+f"(c[3])
        : "r"(a0), "r"(a1), "r"(a2), "r"(a3), "r"(b0), "r"(b1));
}
static __device__ __forceinline__ uint32_t smem_u32(const void* p) {
    uint32_t a;
    asm("{ .reg .u64 t; cvta.to.shared.u64 t, %1; cvt.u32.u64 %0, t; }"
        : "=r"(a) : "l"(p));
    return a;
}
static __device__ __forceinline__ void cp16(uint32_t dst, const void* src) {
    asm volatile("cp.async.cg.shared.global [%0], [%1], 16;" :: "r"(dst), "l"(src));
}
#define CP_COMMIT() asm volatile("cp.async.commit_group;" ::: "memory")
#define CP_WAIT0()  asm volatile("cp.async.wait_group 0;" ::: "memory")

// ---------------------------------------------------------------------------
// Round to tf32 + permute columns within 8-blocks.
// ---------------------------------------------------------------------------
__global__ void round_perm_kernel(const float* __restrict__ in, float* __restrict__ out, int n)
{
    int base = (blockIdx.x * blockDim.x + threadIdx.x) * 8;
    if (base < n) {
        float4 v0 = *(const float4*)(in + base);
        float4 v1 = *(const float4*)(in + base + 4);
        out[base + 0] = tf32r(v0.x);
        out[base + 2] = tf32r(v0.y);
        out[base + 4] = tf32r(v0.z);
        out[base + 6] = tf32r(v0.w);
        out[base + 1] = tf32r(v1.x);
        out[base + 3] = tf32r(v1.y);
        out[base + 5] = tf32r(v1.z);
        out[base + 7] = tf32r(v1.w);
    }
}

// ---------------------------------------------------------------------------
// Transpose + tf32 round + K-permute: out[N,K] = tf32(in[K,N]), K permuted.
// ---------------------------------------------------------------------------
__global__ void transpose_kernel(const float* __restrict__ in, float* __restrict__ out,
                                 int R, int Ccols)
{
    __shared__ float tile[32][33];
    int c = blockIdx.x * 32 + threadIdx.x;
    int r0 = blockIdx.y * 32;
#pragma unroll
    for (int i = 0; i < 32; i += 8)
        tile[threadIdx.y + i][threadIdx.x] =
            tf32r(in[(size_t)(r0 + threadIdx.y + i) * Ccols + c]);
    __syncthreads();
    int oc = blockIdx.y * 32 + threadIdx.x;       // K index
    int j  = oc & 7;
    int ocp = (oc & ~7) + ((j < 4) ? (2 * j) : (2 * (j - 4) + 1));
    int or0 = blockIdx.x * 32;
#pragma unroll
    for (int i = 0; i < 32; i += 8)
        out[(size_t)(or0 + threadIdx.y + i) * R + ocp] = tile[threadIdx.x][threadIdx.y + i];
}

// ---------------------------------------------------------------------------
// mma.sync tf32 GEMM, 2-stage cp.async, K-PERMUTED operands (R15, validated).
// round_out=1 -> tf32-rounded output with N-PERMUTED columns (for flash/qkv).
// ---------------------------------------------------------------------------
constexpr int ASTR = 40;
constexpr int GEMM_SMEM = 2 * 2 * 128 * ASTR * (int)sizeof(float);   // 81920

__global__ __launch_bounds__(256)
void gemm_mma_kernel(const float* __restrict__ A, const float* __restrict__ BT,
                     const float* __restrict__ bias, float* __restrict__ C,
                     int M, int N, int K, int round_out)
{
    extern __shared__ float sm[];
    float* AsBase = sm;                      // [2][128][ASTR]
    float* BsBase = sm + 2 * 128 * ASTR;     // [2][128][ASTR]
    const uint32_t smem0 = smem_u32(sm);

    const int tid  = threadIdx.x;
    const int wid  = tid >> 5;
    const int lane = tid & 31;
    const int gid  = lane >> 2;
    const int tig  = lane & 3;
    const int warp_m = wid & 1;
    const int warp_n = wid >> 1;

    const int row0 = blockIdx.y * 128;
    const int n0   = blockIdx.x * 128;

    const int arow = tid >> 3;               // 0..31
    const int acol = (tid & 7) * 4;          // float offset 0..28
    const float* Ab = A  + (size_t)(row0 + arow) * K + acol;
    const float* Bb = BT + (size_t)(n0  + arow) * K + acol;
    const uint32_t adst0 = smem0 + (uint32_t)(arow * ASTR + acol) * 4;
    const uint32_t bdst0 = adst0 + (uint32_t)(2 * 128 * ASTR) * 4;
    const uint32_t rstep = (uint32_t)(32 * ASTR) * 4;
    const uint32_t bufstep = (uint32_t)(128 * ASTR) * 4;

    float acc[4][4][4];
#pragma unroll
    for (int mi = 0; mi < 4; mi++)
#pragma unroll
        for (int ni = 0; ni < 4; ni++)
#pragma unroll
            for (int r = 0; r < 4; r++) acc[mi][ni][r] = 0.0f;

    const int nchunk = K / 32;

#pragma unroll
    for (int it = 0; it < 4; it++) {
        cp16(adst0 + it * rstep, Ab + (size_t)(it * 32) * K);
        cp16(bdst0 + it * rstep, Bb + (size_t)(it * 32) * K);
    }
    CP_COMMIT();

    for (int c = 0; c < nchunk; c++) {
        const int buf = c & 1;
        const float* As = AsBase + buf * 128 * ASTR;
        const float* Bs = BsBase + buf * 128 * ASTR;

        CP_WAIT0();
        __syncthreads();

        if (c + 1 < nchunk) {
            const float* as = Ab + (size_t)(c + 1) * 32;
            const float* bs = Bb + (size_t)(c + 1) * 32;
            const uint32_t ad = adst0 + (buf ^ 1) * bufstep;
            const uint32_t bd = bdst0 + (buf ^ 1) * bufstep;
#pragma unroll
            for (int it = 0; it < 4; it++) {
                cp16(ad + it * rstep, as + (size_t)(it * 32) * K);
                cp16(bd + it * rstep, bs + (size_t)(it * 32) * K);
            }
            CP_COMMIT();
        }

        const int mbase = warp_m * 64;
        const int nbase = warp_n * 32;
#pragma unroll
        for (int kk = 0; kk < 32; kk += 8) {
            uint32_t afr[4][4];
#pragma unroll
            for (int mi = 0; mi < 4; mi++) {
                const int r = mbase + mi * 16;
                float2 alo = *(const float2*)&As[(r + gid)     * ASTR + kk + tig * 2];
                float2 ahi = *(const float2*)&As[(r + gid + 8) * ASTR + kk + tig * 2];
                afr[mi][0] = __float_as_uint(alo.x);
                afr[mi][1] = __float_as_uint(ahi.x);
                afr[mi][2] = __float_as_uint(alo.y);
                afr[mi][3] = __float_as_uint(ahi.y);
            }
            uint32_t bfr[4][2];
#pragma unroll
            for (int ni = 0; ni < 4; ni++) {
                const int n = nbase + ni * 8 + gid;
                float2 bv = *(const float2*)&Bs[n * ASTR + kk + tig * 2];
                bfr[ni][0] = __float_as_uint(bv.x);
                bfr[ni][1] = __float_as_uint(bv.y);
            }
#pragma unroll
            for (int mi = 0; mi < 4; mi++)
#pragma unroll
                for (int ni = 0; ni < 4; ni++)
                    mma_tf32(acc[mi][ni], afr[mi][0], afr[mi][1], afr[mi][2], afr[mi][3],
                             bfr[ni][0], bfr[ni][1]);
        }
    }

    // epilogue. round_out=1: tf32-round AND write N-permuted columns so the
    // consumer (flash) sees a d-permuted qkv.
    // source cols within 8-block: j0=2tig, j1=2tig+1 -> positions pp0, pp0+2.
    const int pp0 = (tig < 2) ? (4 * tig) : (4 * tig - 7);
#pragma unroll
    for (int mi = 0; mi < 4; mi++) {
        const int r = row0 + warp_m * 64 + mi * 16 + gid;
#pragma unroll
        for (int ni = 0; ni < 4; ni++) {
            const int blk = n0 + warp_n * 32 + ni * 8;
            const float b0 = bias[blk + tig * 2], b1 = bias[blk + tig * 2 + 1];
            if (round_out) {
                float* c0 = C + (size_t)r * N + blk;
                float* c1 = C + (size_t)(r + 8) * N + blk;
                c0[pp0]     = tf32r(acc[mi][ni][0] + b0);
                c0[pp0 + 2] = tf32r(acc[mi][ni][1] + b1);
                c1[pp0]     = tf32r(acc[mi][ni][2] + b0);
                c1[pp0 + 2] = tf32r(acc[mi][ni][3] + b1);
            } else {
                float2 v0 = { acc[mi][ni][0] + b0, acc[mi][ni][1] + b1 };
                float2 v1 = { acc[mi][ni][2] + b0, acc[mi][ni][3] + b1 };
                *(float2*)(C + (size_t)r * N + blk + tig * 2)       = v0;
                *(float2*)(C + (size_t)(r + 8) * N + blk + tig * 2) = v1;
            }
        }
    }
}

// ---------------------------------------------------------------------------
// Flash attention (causal), mma.sync tf32. qkv is d-PERMUTED:
//  - Q/K fragment pairs adjacent -> LDS.64 (KSTR=72 conflict-free)
//  - V d-permutation makes O emerge permuted = layout out-proj wants,
//    so the epilogue is plain float2 stores.
// ---------------------------------------------------------------------------
constexpr int KSTR = 72;   // K tiles (8*gid+2tig mod 32 distinct -> LDS.64 ok)
constexpr int VSTR = 72;   // V tiles (PV B-frag 8*tig+gid pattern, distinct)
constexpr int PSTR = 68;   // Ps staging (P A-frag 4*gid+tig pattern, distinct)
constexpr int FL6_SMEM = (2 * 64 * KSTR + 2 * 64 * VSTR + 128 * PSTR) * (int)sizeof(float); // 108544

__global__ __launch_bounds__(256, 2)
void flash_mma_kernel(const float* __restrict__ qkv, float* __restrict__ out)
{
    extern __shared__ float sm[];
    float* KBuf = sm;                        // [2][64][KSTR]
    float* VBuf = sm + 2 * 64 * KSTR;        // [2][64][VSTR]
    float* Ps   = VBuf + 2 * 64 * VSTR;      // [128][PSTR]
    const uint32_t smem0 = smem_u32(sm);
    const uint32_t voff  = (uint32_t)(2 * 64 * KSTR) * 4;

    const int tid  = threadIdx.x;
    const int wid  = tid >> 5;
    const int lane = tid & 31;
    const int gid  = lane >> 2;
    const int tig  = lane & 3;

    const int qx = 15 - blockIdx.x;          // heavy tiles first
    const int bh = blockIdx.y;
    const int b  = bh >> 4;
    const int h  = bh & 15;
    const int q0 = qx * 128;
    const int rs = 3072;
    const float* base = qkv + (size_t)(b * 2048) * rs + h * 64;

    const int ckey = tid >> 4;               // 0..15
    const int c16f = (tid & 15) * 4;
    const int nkt  = 2 * qx + 2;

    // issue K/V tile 0 into buffer 0 (memory order: already d-permuted)
#pragma unroll
    for (int it = 0; it < 4; it++) {
        const int key = ckey + it * 16;
        const float* ksrc = base + (size_t)key * rs + 1024 + c16f;
        cp16(smem0 + (uint32_t)(key * KSTR + c16f) * 4, ksrc);
        cp16(smem0 + voff + (uint32_t)(key * VSTR + c16f) * 4, ksrc + 1024);
    }
    CP_COMMIT();

    // ---- stage Q tile (exact x0.125; memory order = d-permuted) ----
#pragma unroll
    for (int i = 0; i < 8; i++) {
        int idx = tid + i * 256;
        int row = idx >> 4;
        int dg  = (idx & 15) * 4;
        float4 v = *(const float4*)(base + (size_t)(q0 + row) * rs + dg);
        float* d = &Ps[row * PSTR + dg];
        d[0] = v.x * 0.125f; d[1] = v.y * 0.125f;
        d[2] = v.z * 0.125f; d[3] = v.w * 0.125f;
    }
    __syncthreads();

    const int lr0 = wid * 16 + gid;
    const int lr1 = lr0 + 8;
    uint32_t qf[8][4];
#pragma unroll
    for (int kk = 0; kk < 8; kk++) {
        // permuted: (logical tig, tig+4) at adjacent positions 2tig, 2tig+1
        float2 lo = *(const float2*)&Ps[lr0 * PSTR + kk * 8 + tig * 2];
        float2 hi = *(const float2*)&Ps[lr1 * PSTR + kk * 8 + tig * 2];
        qf[kk][0] = __float_as_uint(lo.x);
        qf[kk][1] = __float_as_uint(hi.x);
        qf[kk][2] = __float_as_uint(lo.y);
        qf[kk][3] = __float_as_uint(hi.y);
    }

    float of[8][4];
#pragma unroll
    for (int ni = 0; ni < 8; ni++)
#pragma unroll
        for (int r = 0; r < 4; r++) of[ni][r] = 0.0f;
    float m0 = -1e30f, m1 = -1e30f, l0 = 0.0f, l1 = 0.0f;

    const int row0g = q0 + lr0;
    const int row1g = row0g + 8;

    for (int kt = 0; kt < nkt; kt++) {
        const int buf = kt & 1;
        const float* Ks = KBuf + buf * 64 * KSTR;
        const float* Vs = VBuf + buf * 64 * VSTR;

        CP_WAIT0();
        __syncthreads();

        if (kt + 1 < nkt) {
            const int kb = (buf ^ 1) * 64;
#pragma unroll
            for (int it = 0; it < 4; it++) {
                const int key = ckey + it * 16;
                const float* ksrc = base + (size_t)((kt + 1) * 64 + key) * rs + 1024 + c16f;
                cp16(smem0 + (uint32_t)((kb + key) * KSTR + c16f) * 4, ksrc);
                cp16(smem0 + voff + (uint32_t)((kb + key) * VSTR + c16f) * 4, ksrc + 1024);
            }
            CP_COMMIT();
        }

        // ---- S = Q K^T  (K d-permuted: B-frag pairs = one LDS.64) ----
        float sf[8][4];
#pragma unroll
        for (int ni = 0; ni < 8; ni++)
#pragma unroll
            for (int r = 0; r < 4; r++) sf[ni][r] = 0.0f;

#pragma unroll
        for (int kk = 0; kk < 8; kk++) {
#pragma unroll
            for (int ni = 0; ni < 8; ni++) {
                float2 bv = *(const float2*)&Ks[(ni * 8 + gid) * KSTR + kk * 8 + tig * 2];
                mma_tf32(sf[ni], qf[kk][0], qf[kk][1], qf[kk][2], qf[kk][3],
                         __float_as_uint(bv.x), __float_as_uint(bv.y));
            }
        }

        // ---- causal mask (diagonal tiles only) ----
        if (kt >= 2 * qx) {
            const int cb = kt * 64 + tig * 2;
#pragma unroll
            for (int ni = 0; ni < 8; ni++) {
                const int c0 = cb + ni * 8, c1 = c0 + 1;
                if (c0 > row0g) sf[ni][0] = -1e30f;
                if (c1 > row0g) sf[ni][1] = -1e30f;
                if (c0 > row1g) sf[ni][2] = -1e30f;
                if (c1 > row1g) sf[ni][3] = -1e30f;
            }
        }

        // ---- online softmax ----
        float mx0 = -1e30f, mx1 = -1e30f;
#pragma unroll
        for (int ni = 0; ni < 8; ni++) {
            mx0 = fmaxf(mx0, fmaxf(sf[ni][0], sf[ni][1]));
            mx1 = fmaxf(mx1, fmaxf(sf[ni][2], sf[ni][3]));
        }
        mx0 = fmaxf(mx0, __shfl_xor_sync(0xffffffffu, mx0, 1));
        mx0 = fmaxf(mx0, __shfl_xor_sync(0xffffffffu, mx0, 2));
        mx1 = fmaxf(mx1, __shfl_xor_sync(0xffffffffu, mx1, 1));
        mx1 = fmaxf(mx1, __shfl_xor_sync(0xffffffffu, mx1, 2));

        const float mn0 = fmaxf(m0, mx0);
        const float mn1 = fmaxf(m1, mx1);
        const float corr0 = __expf(m0 - mn0);
        const float corr1 = __expf(m1 - mn1);
        m0 = mn0; m1 = mn1;

        float ls0 = 0.0f, ls1 = 0.0f;
#pragma unroll
        for (int ni = 0; ni < 8; ni++) {
            sf[ni][0] = __expf(sf[ni][0] - mn0); ls0 += sf[ni][0];
            sf[ni][1] = __expf(sf[ni][1] - mn0); ls0 += sf[ni][1];
            sf[ni][2] = __expf(sf[ni][2] - mn1); ls1 += sf[ni][2];
            sf[ni][3] = __expf(sf[ni][3] - mn1); ls1 += sf[ni][3];
        }
        ls0 += __shfl_xor_sync(0xffffffffu, ls0, 1);
        ls0 += __shfl_xor_sync(0xffffffffu, ls0, 2);
        ls1 += __shfl_xor_sync(0xffffffffu, ls1, 1);
        ls1 += __shfl_xor_sync(0xffffffffu, ls1, 2);
        l0 = l0 * corr0 + ls0;
        l1 = l1 * corr1 + ls1;

#pragma unroll
        for (int ni = 0; ni < 8; ni++) {
            of[ni][0] *= corr0; of[ni][1] *= corr0;
            of[ni][2] *= corr1; of[ni][3] *= corr1;
        }

        // ---- stage P (tf32) for A-operand re-fragmentation ----
#pragma unroll
        for (int ni = 0; ni < 8; ni++) {
            float2 p0 = { tf32r(sf[ni][0]), tf32r(sf[ni][1]) };
            float2 p1 = { tf32r(sf[ni][2]), tf32r(sf[ni][3]) };
            *(float2*)&Ps[lr0 * PSTR + ni * 8 + tig * 2] = p0;
            *(float2*)&Ps[lr1 * PSTR + ni * 8 + tig * 2] = p1;
        }
        __syncthreads();

        // ---- O += P V  (V[key][d-perm]; output cols = permuted d) ----
#pragma unroll
        for (int kk = 0; kk < 8; kk++) {
            uint32_t pa0 = __float_as_uint(Ps[lr0 * PSTR + kk * 8 + tig]);
            uint32_t pa1 = __float_as_uint(Ps[lr1 * PSTR + kk * 8 + tig]);
            uint32_t pa2 = __float_as_uint(Ps[lr0 * PSTR + kk * 8 + tig + 4]);
            uint32_t pa3 = __float_as_uint(Ps[lr1 * PSTR + kk * 8 + tig + 4]);
#pragma unroll
            for (int ni = 0; ni < 8; ni++) {
                uint32_t b0 = __float_as_uint(Vs[(kk * 8 + tig)     * VSTR + ni * 8 + gid]);
                uint32_t b1 = __float_as_uint(Vs[(kk * 8 + tig + 4) * VSTR + ni * 8 + gid]);
                mma_tf32(of[ni], pa0, pa1, pa2, pa3, b0, b1);
            }
        }
    }

    // ---- epilogue: O cols are already permuted d -> plain float2 stores ----
    const float inv0 = 1.0f / l0;
    const float inv1 = 1.0f / l1;
    float* o0 = out + (size_t)(b * 2048 + row0g) * 1024 + h * 64;
    float* o1 = o0 + (size_t)8 * 1024;
#pragma unroll
    for (int ni = 0; ni < 8; ni++) {
        float2 v0 = { tf32r(of[ni][0] * inv0), tf32r(of[ni][1] * inv0) };
        float2 v1 = { tf32r(of[ni][2] * inv1), tf32r(of[ni][3] * inv1) };
        *(float2*)(o0 + ni * 8 + tig * 2) = v0;
        *(float2*)(o1 + ni * 8 + tig * 2) = v1;
    }
}

// ---------------------------------------------------------------------------
// kernel_launch
// ---------------------------------------------------------------------------
extern "C" void kernel_launch(void* const* d_in, const int* in_sizes, int n_in,
                              void* d_out, int out_size)
{
    const float* x     = (const float*)d_in[0];   // [4096, 1024]
    const float* w_qkv = (const float*)d_in[1];   // [1024, 3072]
    const float* b_qkv = (const float*)d_in[2];   // [3072]
    const float* w_out = (const float*)d_in[3];   // [1024, 1024]
    const float* b_out = (const float*)d_in[4];   // [1024]
    float* out = (float*)d_out;                   // [4096, 1024]

    float *qkv = nullptr, *attn = nullptr, *wt = nullptr, *xr = nullptr;
    cudaGetSymbolAddress((void**)&qkv,  g_qkv);
    cudaGetSymbolAddress((void**)&attn, g_attn);
    cudaGetSymbolAddress((void**)&wt,   g_wt);
    cudaGetSymbolAddress((void**)&xr,   g_xr);
    float* wt_qkv = wt;                      // [3072, 1024]
    float* wt_out = wt + 3072 * 1024;        // [1024, 1024]

    cudaFuncSetAttribute(gemm_mma_kernel,
                         cudaFuncAttributeMaxDynamicSharedMemorySize, GEMM_SMEM);
    cudaFuncSetAttribute(flash_mma_kernel,
                         cudaFuncAttributeMaxDynamicSharedMemorySize, FL6_SMEM);

    // 0) pre-round + K-permute x; transpose + round + K-permute weights
    round_perm_kernel<<<2048, 256>>>(x, xr, 4096 * 1024);
    {
        dim3 blk(32, 8);
        transpose_kernel<<<dim3(3072 / 32, 1024 / 32), blk>>>(w_qkv, wt_qkv, 1024, 3072);
        transpose_kernel<<<dim3(1024 / 32, 1024 / 32), blk>>>(w_out, wt_out, 1024, 1024);
    }

    // 1) QKV projection (tf32-rounded, d-permuted output for flash)
    {
        dim3 grid(3072 / 128, 4096 / 128);
        gemm_mma_kernel<<<grid, 256, GEMM_SMEM>>>(xr, wt_qkv, b_qkv, qkv, 4096, 3072, 1024, 1);
    }

    // 2) Causal flash attention -> g_attn (tf32-rounded, d-permuted cols)
    {
        dim3 grid(16, 2 * 16);
        flash_mma_kernel<<<grid, 256, FL6_SMEM>>>(qkv, attn);
    }

    // 3) Output projection (full-precision output)
    {
        dim3 grid(1024 / 128, 4096 / 128);
        gemm_mma_kernel<<<grid, 256, GEMM_SMEM>>>(attn, wt_out, b_out, out, 4096, 1024, 1024, 0);
    }
}